// round 9
// baseline (speedup 1.0000x reference)
#include <cuda_runtime.h>
#include <math.h>
#include <cstdint>

#define BD   1024
#define HD   512
#define TENC 384
#define TDEC 128
#define ID   128
#define NBLK 256
#define NTHR 256

#define ROWB 80            // smem row stride bytes (16 floats + 16B pad)
#define STB  15360         // stage bytes: A 128*80 + B 64*80
#define NST  4

// ---------------- static device scratch ------------------------------------
// Ping-pong h buffers: [h0 | h1] per batch row, row stride 1024.
// Timestep t writes g_h[t&1], reads previous h from g_h[!(t&1)].
// This removes the WAR hazard (phase reads h[t-1] via cp.async while its
// epilogue writes h[t]) that corrupted rounds 7/8 under occupancy-2 skew.
__device__ __align__(16) float g_hA[BD * 1024];
__device__ __align__(16) float g_hB[BD * 1024];
__device__ __align__(16) float g_c0 [BD * HD];
__device__ __align__(16) float g_c1 [BD * HD];
__device__ __align__(16) float g_din[BD * ID];
// tf32-pre-rounded weight copies
__device__ __align__(16) float g_rWih0[2048 * 128];
__device__ __align__(16) float g_rWhh0[2048 * 512];
__device__ __align__(16) float g_rWih1[2048 * 512];
__device__ __align__(16) float g_rWhh1[2048 * 512];
__device__ unsigned          g_bar_cnt;
__device__ volatile unsigned g_bar_gen;

// ---------------- helpers --------------------------------------------------
__device__ __forceinline__ uint32_t smem_u32(const void* p) {
    uint32_t a;
    asm("{ .reg .u64 t; cvta.to.shared.u64 t, %1; cvt.u32.u64 %0, t; }"
        : "=r"(a) : "l"(p));
    return a;
}
__device__ __forceinline__ float f2tf(float f) {
    unsigned u;
    asm("cvt.rna.tf32.f32 %0, %1;" : "=r"(u) : "f"(f));
    return __uint_as_float(u);
}
__device__ __forceinline__ float sigf(float x) {
    return __fdividef(1.f, 1.f + __expf(-x));
}
__device__ __forceinline__ float tanh_(float x) {
    float e = __expf(-2.f * fabsf(x));
    float t = __fdividef(1.f - e, 1.f + e);
    return copysignf(t, x);
}
__device__ __forceinline__ void cp16(uint32_t dst, const float* src) {
    asm volatile("cp.async.cg.shared.global [%0], [%1], 16;"
                 :: "r"(dst), "l"(src) : "memory");
}
__device__ __forceinline__ void mma8(float* c, uint32_t a0, uint32_t a1,
                                     uint32_t a2, uint32_t a3,
                                     uint32_t b0, uint32_t b1) {
    asm volatile("mma.sync.aligned.m16n8k8.row.col.f32.tf32.tf32.f32 "
                 "{%0,%1,%2,%3}, {%4,%5,%6,%7}, {%8,%9}, {%0,%1,%2,%3};"
                 : "+f"(c[0]), "+f"(c[1]), "+f"(c[2]), "+f"(c[3])
                 : "r"(a0), "r"(a1), "r"(a2), "r"(a3), "r"(b0), "r"(b1));
}
#define LDSM4(r, a)                                                          \
    asm volatile("ldmatrix.sync.aligned.m8n8.x4.shared.b16 {%0,%1,%2,%3}, [%4];" \
        : "=r"((r)[0]), "=r"((r)[1]), "=r"((r)[2]), "=r"((r)[3]) : "r"(a))

// L1-bypassing float4 load (L2-coherent cross-CTA read)
__device__ __forceinline__ float4 ldcg4(const float* p) {
    float4 v;
    asm volatile("ld.global.cg.v4.f32 {%0,%1,%2,%3}, [%4];"
                 : "=f"(v.x), "=f"(v.y), "=f"(v.z), "=f"(v.w) : "l"(p));
    return v;
}

// ---------------- grid barrier ---------------------------------------------
__device__ __forceinline__ void gridbar() {
    __syncthreads();
    if (threadIdx.x == 0) {
        unsigned gen = g_bar_gen;
        __threadfence();
        if (atomicAdd(&g_bar_cnt, 1u) == NBLK - 1u) {
            g_bar_cnt = 0u;
            __threadfence();
            g_bar_gen = gen + 1u;
        } else {
            while (g_bar_gen == gen) { __nanosleep(32); }
        }
        __threadfence();
    }
    __syncthreads();
}

// ---------------- init: states, din seed, weight rounding -------------------
__device__ void init_phase(const float* __restrict__ x,
                           const float* __restrict__ Wih0,
                           const float* __restrict__ Whh0,
                           const float* __restrict__ Wih1,
                           const float* __restrict__ Whh1)
{
    const int g = blockIdx.x * NTHR + threadIdx.x;  // 0..65535
    const int GT = NBLK * NTHR;                     // 65536
#pragma unroll
    for (int i = 0; i < 16; i++) { g_hA[g + i * GT] = 0.f; g_hB[g + i * GT] = 0.f; }
#pragma unroll
    for (int i = 0; i < 8; i++) { g_c0[g + i * GT] = 0.f; g_c1[g + i * GT] = 0.f; }
#pragma unroll
    for (int i = 0; i < 2; i++) {
        int idx = g + i * GT;
        int b = idx >> 7, col = idx & 127;
        g_din[idx] = f2tf(x[(size_t)b * (TENC * ID) + (size_t)(TENC - 1) * ID + col]);
    }
    for (int i = g; i < 2048 * 128; i += GT) g_rWih0[i] = f2tf(Wih0[i]);
    for (int i = g; i < 2048 * 512; i += GT) {
        g_rWhh0[i] = f2tf(Whh0[i]);
        g_rWih1[i] = f2tf(Wih1[i]);
        g_rWhh1[i] = f2tf(Whh1[i]);
    }
}

// ---------------- fused GEMM + gates phase ----------------------------------
// CTA tile: 128 batch rows x 64 gate cols ({i,f,g,o} x 16 j at j0).
// 256 CTAs = 8 m-groups x 32 j-groups.
__device__ void phase_layer(char* smem, float* sbias,
                            const float* A1, size_t lda1, int KA1,
                            const float* A2, int lda2,
                            const float* W1, int ldw1, int KW1,
                            const float* W2, int ldw2,
                            const float* bih, const float* bhh,
                            float* cbuf, float* hdst, int KT)
{
    const int tid = threadIdx.x;
    const int m0 = (blockIdx.x >> 5) * 128;
    const int j0 = (blockIdx.x & 31) * 16;
    const int nch = KT >> 4;             // #k16 tiles

    if (tid < 64) {
        int n = (tid >> 4) * 512 + j0 + (tid & 15);
        sbias[tid] = bih[n] + bhh[n];
    }

    // -------- loaders: threads 0-127 -> A rows (4x cp16),
    //                   threads 128-255 -> B rows (2 thr/row, 2x cp16)
    const bool isA = tid < 128;
    const int  lt  = tid & 127;
    const int  brow = lt >> 1;                 // 0..63
    const int  bhalf = lt & 1;                 // 0/1 (8 floats each)
    const uint32_t sA = smem_u32(smem);
    const uint32_t sB = sA + 10240u;
    const uint32_t srowA = sA + (uint32_t)lt * ROWB;
    const uint32_t srowB = sB + (uint32_t)brow * ROWB + (uint32_t)bhalf * 32u;
    const int nrow = (brow >> 4) * 512 + j0 + (brow & 15);   // weight row

    auto load_stage = [&](int ch) {
        int st = ch & (NST - 1);
        int k0 = ch * 16;
        if (isA) {
            const float* src = (k0 < KA1)
                ? A1 + (size_t)(m0 + lt) * lda1 + k0
                : A2 + (size_t)(m0 + lt) * lda2 + (k0 - KA1);
            uint32_t dst = srowA + (uint32_t)st * STB;
            cp16(dst,      src);
            cp16(dst + 16, src + 4);
            cp16(dst + 32, src + 8);
            cp16(dst + 48, src + 12);
        } else {
            const float* src = (k0 < KW1)
                ? W1 + (size_t)nrow * ldw1 + k0 + bhalf * 8
                : W2 + (size_t)nrow * ldw2 + (k0 - KW1) + bhalf * 8;
            uint32_t dst = srowB + (uint32_t)st * STB;
            cp16(dst,      src);
            cp16(dst + 16, src + 4);
        }
        asm volatile("cp.async.commit_group;" ::: "memory");
    };

    // -------- fragment addressing (warp tile 64m x 16n)
    const int lane = tid & 31, warp = tid >> 5;
    const int wm = (warp >> 2) * 64;
    const int wn = (warp & 3) * 16;
    const uint32_t offA = sA + (uint32_t)((((lane >> 3) & 1) * 8 + (lane & 7)) * ROWB)
                             + (uint32_t)((lane >> 4) * 16) + (uint32_t)wm * ROWB;
    const uint32_t offB = sB + (uint32_t)((lane & 7) * ROWB)
                             + (uint32_t)((lane >> 3) * 16) + (uint32_t)wn * ROWB;

    float acc[4][2][4];
#pragma unroll
    for (int mi = 0; mi < 4; mi++)
#pragma unroll
        for (int ni = 0; ni < 2; ni++)
#pragma unroll
            for (int r = 0; r < 4; r++) acc[mi][ni][r] = 0.f;

    load_stage(0); load_stage(1); load_stage(2);

    for (int ch = 0; ch < nch; ch++) {
        if (ch + 2 < nch)      asm volatile("cp.async.wait_group 2;" ::: "memory");
        else if (ch + 1 < nch) asm volatile("cp.async.wait_group 1;" ::: "memory");
        else                   asm volatile("cp.async.wait_group 0;" ::: "memory");
        __syncthreads();
        if (ch + 3 < nch) load_stage(ch + 3);

        const uint32_t so = (uint32_t)(ch & (NST - 1)) * STB;
        uint32_t fb[2][4];
#pragma unroll
        for (int ni = 0; ni < 2; ni++)
            LDSM4(fb[ni], offB + so + (uint32_t)(ni * 8 * ROWB));
#pragma unroll
        for (int mi = 0; mi < 4; mi++) {
            uint32_t fa0[4], fa1[4];
            LDSM4(fa0, offA + so + (uint32_t)(mi * 16 * ROWB));
            LDSM4(fa1, offA + so + (uint32_t)(mi * 16 * ROWB) + 32u);
#pragma unroll
            for (int ni = 0; ni < 2; ni++) {
                mma8(acc[mi][ni], fa0[0], fa0[1], fa0[2], fa0[3], fb[ni][0], fb[ni][1]);
                mma8(acc[mi][ni], fa1[0], fa1[1], fa1[2], fa1[3], fb[ni][2], fb[ni][3]);
            }
        }
    }

    // -------- epilogue: accs -> smem z-buffer (128 x 68), then gates
    float* zb = (float*)smem;
    __syncthreads();
    {
        const int gid = lane >> 2, t4 = lane & 3;
#pragma unroll
        for (int mi = 0; mi < 4; mi++) {
            int r0 = wm + mi * 16 + gid;
#pragma unroll
            for (int ni = 0; ni < 2; ni++) {
                int c = wn + ni * 8 + t4 * 2;
                *(float2*)&zb[(size_t)r0 * 68 + c]       = make_float2(acc[mi][ni][0], acc[mi][ni][1]);
                *(float2*)&zb[(size_t)(r0 + 8) * 68 + c] = make_float2(acc[mi][ni][2], acc[mi][ni][3]);
            }
        }
    }
    __syncthreads();
    {
        const int row = tid >> 1;            // 0..127
        const int jh  = (tid & 1) * 8;       // 0 or 8
        const int m   = m0 + row;
        const float* zr = zb + (size_t)row * 68;
        float* cp_ = cbuf + (size_t)m * HD + j0 + jh;
        float* hp_ = hdst + (size_t)m * 1024 + j0 + jh;
#pragma unroll
        for (int jj = 0; jj < 8; jj++) {
            int j = jh + jj;
            float zi = zr[j]      + sbias[j];
            float zf = zr[16 + j] + sbias[16 + j];
            float zg = zr[32 + j] + sbias[32 + j];
            float zo = zr[48 + j] + sbias[48 + j];
            float c = sigf(zf) * cp_[jj] + sigf(zi) * tanh_(zg);
            cp_[jj] = c;
            hp_[jj] = f2tf(sigf(zo) * tanh_(c));
        }
    }
    __syncthreads();
}

// ---------------- fc phase (decoder projection), 32m x 16n tiles -------------
__device__ void fc_phase(char* smem, const float* __restrict__ hcur,
                         const float* __restrict__ fcw,
                         const float* __restrict__ fcb,
                         float* __restrict__ out, int t)
{
    const int m0 = (blockIdx.x >> 3) * 32;     // 32 batch rows
    const int c0 = (blockIdx.x & 7) * 16;      // 16 out cols
    const int tid = threadIdx.x;
    float* hs = (float*)smem;                  // 32 x 136 floats

    const int r  = tid >> 3;                   // 0..31 output row
    const int cq = c0 + (tid & 7) * 2;         // 2 output cols
    float a0 = 0.f, a1 = 0.f;

    for (int kc = 0; kc < HD; kc += 128) {
        __syncthreads();
        {   // load h1 tile 32 x 128 (cross-CTA data: bypass L1)
            int rr = tid >> 3, u = tid & 7;
            const float* src = hcur + (size_t)(m0 + rr) * 1024 + 512 + kc + u * 16;
            float* dst = hs + (size_t)rr * 136 + u * 16;
#pragma unroll
            for (int q = 0; q < 4; q++)
                *(float4*)(dst + q * 4) = ldcg4(src + q * 4);
        }
        __syncthreads();
        const float* hr = hs + (size_t)r * 136;
        const float4* w0 = (const float4*)(fcw + (size_t)(cq + 0) * HD + kc);
        const float4* w1 = (const float4*)(fcw + (size_t)(cq + 1) * HD + kc);
#pragma unroll 8
        for (int k4 = 0; k4 < 32; k4++) {
            float4 h4 = *(const float4*)(hr + k4 * 4);
            float4 v0 = __ldg(w0 + k4), v1 = __ldg(w1 + k4);
            a0 += h4.x * v0.x + h4.y * v0.y + h4.z * v0.z + h4.w * v0.w;
            a1 += h4.x * v1.x + h4.y * v1.y + h4.z * v1.z + h4.w * v1.w;
        }
    }
    float2 res = make_float2(a0 + fcb[cq], a1 + fcb[cq + 1]);
    *(float2*)(out + (size_t)(m0 + r) * (TDEC * ID) + (size_t)t * ID + cq) = res;
    float2 dv = make_float2(f2tf(res.x), f2tf(res.y));
    *(float2*)(g_din + (size_t)(m0 + r) * ID + cq) = dv;
    __syncthreads();
}

// ---------------- persistent kernel -----------------------------------------
__global__ void __launch_bounds__(NTHR, 2)
lstm_persistent(const float* __restrict__ x,
                const float* __restrict__ Wih0, const float* __restrict__ Whh0,
                const float* __restrict__ bih0, const float* __restrict__ bhh0,
                const float* __restrict__ Wih1, const float* __restrict__ Whh1,
                const float* __restrict__ bih1, const float* __restrict__ bhh1,
                const float* __restrict__ fcw,  const float* __restrict__ fcb,
                float* __restrict__ out)
{
    extern __shared__ char dyn[];        // NST * STB = 61440 B
    __shared__ float s_bias[64];

    init_phase(x, Wih0, Whh0, Wih1, Whh1);
    gridbar();

    // ping-pong: timestep t writes cur = buf[t&1], reads prev = buf[!(t&1)]
    for (int t = 0; t < TENC; t++) {
        float* cur  = (t & 1) ? g_hB : g_hA;
        float* prev = (t & 1) ? g_hA : g_hB;
        // layer0: A = [x_t | h0_prev], writes h0 -> cur[:,0:512]
        phase_layer(dyn, s_bias,
                    x + (size_t)t * ID, (size_t)TENC * ID, 128, prev, 1024,
                    g_rWih0, 128, 128, g_rWhh0, 512,
                    bih0, bhh0, g_c0, cur, 640);
        gridbar();
        // layer1: A = [h0_cur | h1_prev], writes h1 -> cur[:,512:1024]
        phase_layer(dyn, s_bias,
                    cur, 1024, 512, prev + 512, 1024,
                    g_rWih1, 512, 512, g_rWhh1, 512,
                    bih1, bhh1, g_c1, cur + 512, 1024);
        gridbar();
    }

    for (int t = 0; t < TDEC; t++) {
        float* cur  = (t & 1) ? g_hB : g_hA;   // TENC even: continues parity
        float* prev = (t & 1) ? g_hA : g_hB;
        phase_layer(dyn, s_bias,
                    g_din, ID, 128, prev, 1024,
                    g_rWih0, 128, 128, g_rWhh0, 512,
                    bih0, bhh0, g_c0, cur, 640);
        gridbar();
        phase_layer(dyn, s_bias,
                    cur, 1024, 512, prev + 512, 1024,
                    g_rWih1, 512, 512, g_rWhh1, 512,
                    bih1, bhh1, g_c1, cur + 512, 1024);
        gridbar();
        fc_phase(dyn, cur, fcw, fcb, out, t);
        gridbar();
    }
}

// ---------------- entry ------------------------------------------------------
extern "C" void kernel_launch(void* const* d_in, const int* in_sizes, int n_in,
                              void* d_out, int out_size)
{
    const int smem = NST * STB;          // 61440
    cudaFuncSetAttribute(lstm_persistent,
                         cudaFuncAttributeMaxDynamicSharedMemorySize, smem);
    lstm_persistent<<<NBLK, NTHR, smem>>>(
        (const float*)d_in[0],
        (const float*)d_in[1], (const float*)d_in[2],
        (const float*)d_in[3], (const float*)d_in[4],
        (const float*)d_in[5], (const float*)d_in[6],
        (const float*)d_in[7], (const float*)d_in[8],
        (const float*)d_in[9], (const float*)d_in[10],
        (float*)d_out);
}

// round 10
// speedup vs baseline: 1.2396x; 1.2396x over previous
#include <cuda_runtime.h>
#include <math.h>
#include <cstdint>

#define BD   1024
#define HD   512
#define TENC 384
#define TDEC 128
#define ID   128
#define NBLK 128
#define NTHR 512

#define ROWB 144           // smem row stride bytes (32 floats + 16B pad)
#define TILEB (128 * ROWB) // 18432 per operand tile
#define STB  (2 * TILEB)   // 36864 per stage (A + B)
#define NST  3

// ---------------- static device scratch ------------------------------------
// Ping-pong h buffers: [h0 | h1] per batch row, row stride 1024.
__device__ __align__(16) float g_hA[BD * 1024];
__device__ __align__(16) float g_hB[BD * 1024];
__device__ __align__(16) float g_c0 [BD * HD];
__device__ __align__(16) float g_c1 [BD * HD];
__device__ __align__(16) float g_din[BD * ID];
// tf32-pre-rounded weight copies
__device__ __align__(16) float g_rWih0[2048 * 128];
__device__ __align__(16) float g_rWhh0[2048 * 512];
__device__ __align__(16) float g_rWih1[2048 * 512];
__device__ __align__(16) float g_rWhh1[2048 * 512];
__device__ unsigned          g_bar_cnt;
__device__ volatile unsigned g_bar_gen;

// ---------------- helpers --------------------------------------------------
__device__ __forceinline__ uint32_t smem_u32(const void* p) {
    uint32_t a;
    asm("{ .reg .u64 t; cvta.to.shared.u64 t, %1; cvt.u32.u64 %0, t; }"
        : "=r"(a) : "l"(p));
    return a;
}
__device__ __forceinline__ float f2tf(float f) {
    unsigned u;
    asm("cvt.rna.tf32.f32 %0, %1;" : "=r"(u) : "f"(f));
    return __uint_as_float(u);
}
__device__ __forceinline__ float sigf(float x) {
    return __fdividef(1.f, 1.f + __expf(-x));
}
__device__ __forceinline__ float tanh_(float x) {
    float e = __expf(-2.f * fabsf(x));
    float t = __fdividef(1.f - e, 1.f + e);
    return copysignf(t, x);
}
__device__ __forceinline__ void cp16(uint32_t dst, const float* src) {
    asm volatile("cp.async.cg.shared.global [%0], [%1], 16;"
                 :: "r"(dst), "l"(src) : "memory");
}
__device__ __forceinline__ void mma8(float* c, uint32_t a0, uint32_t a1,
                                     uint32_t a2, uint32_t a3,
                                     uint32_t b0, uint32_t b1) {
    asm volatile("mma.sync.aligned.m16n8k8.row.col.f32.tf32.tf32.f32 "
                 "{%0,%1,%2,%3}, {%4,%5,%6,%7}, {%8,%9}, {%0,%1,%2,%3};"
                 : "+f"(c[0]), "+f"(c[1]), "+f"(c[2]), "+f"(c[3])
                 : "r"(a0), "r"(a1), "r"(a2), "r"(a3), "r"(b0), "r"(b1));
}
#define LDSM4(r, a)                                                          \
    asm volatile("ldmatrix.sync.aligned.m8n8.x4.shared.b16 {%0,%1,%2,%3}, [%4];" \
        : "=r"((r)[0]), "=r"((r)[1]), "=r"((r)[2]), "=r"((r)[3]) : "r"(a))

__device__ __forceinline__ float4 ldcg4(const float* p) {
    float4 v;
    asm volatile("ld.global.cg.v4.f32 {%0,%1,%2,%3}, [%4];"
                 : "=f"(v.x), "=f"(v.y), "=f"(v.z), "=f"(v.w) : "l"(p));
    return v;
}

// ---------------- grid barrier ---------------------------------------------
__device__ __forceinline__ void gridbar() {
    __syncthreads();
    if (threadIdx.x == 0) {
        unsigned gen = g_bar_gen;
        __threadfence();
        if (atomicAdd(&g_bar_cnt, 1u) == NBLK - 1u) {
            g_bar_cnt = 0u;
            __threadfence();
            g_bar_gen = gen + 1u;
        } else {
            while (g_bar_gen == gen) { __nanosleep(32); }
        }
        __threadfence();
    }
    __syncthreads();
}

// ---------------- init: states, din seed, weight rounding -------------------
__device__ void init_phase(const float* __restrict__ x,
                           const float* __restrict__ Wih0,
                           const float* __restrict__ Whh0,
                           const float* __restrict__ Wih1,
                           const float* __restrict__ Whh1)
{
    const int g = blockIdx.x * NTHR + threadIdx.x;  // 0..65535
    const int GT = NBLK * NTHR;                     // 65536
#pragma unroll
    for (int i = 0; i < 16; i++) { g_hA[g + i * GT] = 0.f; g_hB[g + i * GT] = 0.f; }
#pragma unroll
    for (int i = 0; i < 8; i++) { g_c0[g + i * GT] = 0.f; g_c1[g + i * GT] = 0.f; }
#pragma unroll
    for (int i = 0; i < 2; i++) {
        int idx = g + i * GT;
        int b = idx >> 7, col = idx & 127;
        g_din[idx] = f2tf(x[(size_t)b * (TENC * ID) + (size_t)(TENC - 1) * ID + col]);
    }
    for (int i = g; i < 2048 * 128; i += GT) g_rWih0[i] = f2tf(Wih0[i]);
    for (int i = g; i < 2048 * 512; i += GT) {
        g_rWhh0[i] = f2tf(Whh0[i]);
        g_rWih1[i] = f2tf(Wih1[i]);
        g_rWhh1[i] = f2tf(Whh1[i]);
    }
}

// ---------------- fused GEMM + gates phase ----------------------------------
// CTA tile: 128 batch rows x 128 gate cols ({i,f,g,o} x 32 j at j0).
// 128 CTAs = 8 m-groups x 16 j-groups. 512 threads (16 warps, 4x4 warp grid).
__device__ void phase_layer(char* smem, float* sbias,
                            const float* A1, size_t lda1, int KA1,
                            const float* A2, int lda2,
                            const float* W1, int ldw1, int KW1,
                            const float* W2, int ldw2,
                            const float* bih, const float* bhh,
                            float* cbuf, float* hdst, int KT)
{
    const int tid = threadIdx.x;
    const int m0 = (blockIdx.x >> 4) * 128;
    const int j0 = (blockIdx.x & 15) * 32;
    const int nch = KT >> 5;             // #k32 chunks

    if (tid < 128) {
        int n = (tid >> 5) * 512 + j0 + (tid & 31);
        sbias[tid] = bih[n] + bhh[n];
    }

    // -------- loaders: threads 0-255 -> A (2 thr/row), 256-511 -> B --------
    const bool isA = tid < 256;
    const int  lt  = tid & 255;
    const int  row = lt >> 1;                  // 0..127
    const int  half = lt & 1;                  // 0/1: 16-float halves
    const uint32_t sA = smem_u32(smem);
    const uint32_t sB = sA + (uint32_t)TILEB;
    const uint32_t srow = (isA ? sA : sB) + (uint32_t)row * ROWB + (uint32_t)half * 64u;
    const int nrow = (row >> 5) * 512 + j0 + (row & 31);   // B weight row

    auto load_stage = [&](int ch) {
        int st = ch - (ch / NST) * NST;
        int k0 = ch * 32;
        const float* src;
        if (isA) src = (k0 < KA1) ? A1 + (size_t)(m0 + row) * lda1 + k0
                                  : A2 + (size_t)(m0 + row) * lda2 + (k0 - KA1);
        else     src = (k0 < KW1) ? W1 + (size_t)nrow * ldw1 + k0
                                  : W2 + (size_t)nrow * ldw2 + (k0 - KW1);
        src += half * 16;
        uint32_t dst = srow + (uint32_t)st * STB;
        cp16(dst,      src);
        cp16(dst + 16, src + 4);
        cp16(dst + 32, src + 8);
        cp16(dst + 48, src + 12);
        asm volatile("cp.async.commit_group;" ::: "memory");
    };

    // -------- fragment addressing (warp tile 32m x 32n; 4x4 warp grid) -----
    const int lane = tid & 31, warp = tid >> 5;
    const int wm = (warp >> 2) * 32;
    const int wn = (warp & 3) * 32;
    const uint32_t offA = sA + (uint32_t)((((lane >> 3) & 1) * 8 + (lane & 7)) * ROWB)
                             + (uint32_t)((lane >> 4) * 16) + (uint32_t)wm * ROWB;
    const uint32_t offB = sB + (uint32_t)((lane & 7) * ROWB)
                             + (uint32_t)((lane >> 3) * 16) + (uint32_t)wn * ROWB;

    float acc[2][4][4];
#pragma unroll
    for (int mi = 0; mi < 2; mi++)
#pragma unroll
        for (int ni = 0; ni < 4; ni++)
#pragma unroll
            for (int r = 0; r < 4; r++) acc[mi][ni][r] = 0.f;

    load_stage(0); load_stage(1);

    for (int ch = 0; ch < nch; ch++) {
        if (ch + 1 < nch) asm volatile("cp.async.wait_group 1;" ::: "memory");
        else              asm volatile("cp.async.wait_group 0;" ::: "memory");
        __syncthreads();
        if (ch + 2 < nch) load_stage(ch + 2);

        int st = ch - (ch / NST) * NST;
        const uint32_t so = (uint32_t)st * STB;
#pragma unroll
        for (int h = 0; h < 2; h++) {          // two k16 halves of the k32 chunk
            uint32_t fb[4][4];
#pragma unroll
            for (int ni = 0; ni < 4; ni++)
                LDSM4(fb[ni], offB + so + (uint32_t)(ni * 8 * ROWB) + (uint32_t)(h * 64));
#pragma unroll
            for (int mi = 0; mi < 2; mi++) {
                uint32_t fa0[4], fa1[4];
                LDSM4(fa0, offA + so + (uint32_t)(mi * 16 * ROWB) + (uint32_t)(h * 64));
                LDSM4(fa1, offA + so + (uint32_t)(mi * 16 * ROWB) + (uint32_t)(h * 64) + 32u);
#pragma unroll
                for (int ni = 0; ni < 4; ni++) {
                    mma8(acc[mi][ni], fa0[0], fa0[1], fa0[2], fa0[3], fb[ni][0], fb[ni][1]);
                    mma8(acc[mi][ni], fa1[0], fa1[1], fa1[2], fa1[3], fb[ni][2], fb[ni][3]);
                }
            }
        }
    }

    // -------- epilogue: accs -> smem z-buffer (128 x 132), then gates -------
    float* zb = (float*)smem;
    __syncthreads();
    {
        const int gid = lane >> 2, t4 = lane & 3;
#pragma unroll
        for (int mi = 0; mi < 2; mi++) {
            int r0 = wm + mi * 16 + gid;
#pragma unroll
            for (int ni = 0; ni < 4; ni++) {
                int c = wn + ni * 8 + t4 * 2;
                *(float2*)&zb[(size_t)r0 * 132 + c]       = make_float2(acc[mi][ni][0], acc[mi][ni][1]);
                *(float2*)&zb[(size_t)(r0 + 8) * 132 + c] = make_float2(acc[mi][ni][2], acc[mi][ni][3]);
            }
        }
    }
    __syncthreads();
    {
        const int row_ = tid >> 2;           // 0..127
        const int jq   = (tid & 3) * 8;      // 8 j's per thread
        const int m    = m0 + row_;
        const float* zr = zb + (size_t)row_ * 132;
        float* cp_ = cbuf + (size_t)m * HD + j0 + jq;
        float* hp_ = hdst + (size_t)m * 1024 + j0 + jq;
#pragma unroll
        for (int jj = 0; jj < 8; jj++) {
            int j = jq + jj;
            float zi = zr[j]      + sbias[j];
            float zf = zr[32 + j] + sbias[32 + j];
            float zg = zr[64 + j] + sbias[64 + j];
            float zo = zr[96 + j] + sbias[96 + j];
            float c = sigf(zf) * cp_[jj] + sigf(zi) * tanh_(zg);
            cp_[jj] = c;
            hp_[jj] = f2tf(sigf(zo) * tanh_(c));
        }
    }
    __syncthreads();
}

// ---------------- fc phase (decoder projection), 32m x 32n tiles -------------
__device__ void fc_phase(char* smem, const float* __restrict__ hcur,
                         const float* __restrict__ fcw,
                         const float* __restrict__ fcb,
                         float* __restrict__ out, int t)
{
    const int m0 = (blockIdx.x >> 2) * 32;     // 32 batch rows
    const int c0 = (blockIdx.x & 3) * 32;      // 32 out cols
    const int tid = threadIdx.x;
    float* hs = (float*)smem;                  // 32 x 136 floats

    const int r  = tid >> 4;                   // 0..31 output row
    const int cq = c0 + (tid & 15) * 2;        // 2 output cols
    float a0 = 0.f, a1 = 0.f;

    for (int kc = 0; kc < HD; kc += 128) {
        __syncthreads();
        {   // load h1 tile 32 x 128 (cross-CTA: bypass L1)
            int rr = tid >> 4, u = tid & 15;
            const float* src = hcur + (size_t)(m0 + rr) * 1024 + 512 + kc + u * 8;
            float* dst = hs + (size_t)rr * 136 + u * 8;
            *(float4*)(dst)     = ldcg4(src);
            *(float4*)(dst + 4) = ldcg4(src + 4);
        }
        __syncthreads();
        const float* hr = hs + (size_t)r * 136;
        const float4* w0 = (const float4*)(fcw + (size_t)(cq + 0) * HD + kc);
        const float4* w1 = (const float4*)(fcw + (size_t)(cq + 1) * HD + kc);
#pragma unroll 8
        for (int k4 = 0; k4 < 32; k4++) {
            float4 h4 = *(const float4*)(hr + k4 * 4);
            float4 v0 = __ldg(w0 + k4), v1 = __ldg(w1 + k4);
            a0 += h4.x * v0.x + h4.y * v0.y + h4.z * v0.z + h4.w * v0.w;
            a1 += h4.x * v1.x + h4.y * v1.y + h4.z * v1.z + h4.w * v1.w;
        }
    }
    float2 res = make_float2(a0 + fcb[cq], a1 + fcb[cq + 1]);
    *(float2*)(out + (size_t)(m0 + r) * (TDEC * ID) + (size_t)t * ID + cq) = res;
    float2 dv = make_float2(f2tf(res.x), f2tf(res.y));
    *(float2*)(g_din + (size_t)(m0 + r) * ID + cq) = dv;
    __syncthreads();
}

// ---------------- persistent kernel -----------------------------------------
__global__ void __launch_bounds__(NTHR, 1)
lstm_persistent(const float* __restrict__ x,
                const float* __restrict__ Wih0, const float* __restrict__ Whh0,
                const float* __restrict__ bih0, const float* __restrict__ bhh0,
                const float* __restrict__ Wih1, const float* __restrict__ Whh1,
                const float* __restrict__ bih1, const float* __restrict__ bhh1,
                const float* __restrict__ fcw,  const float* __restrict__ fcb,
                float* __restrict__ out)
{
    extern __shared__ char dyn[];        // NST * STB = 110592 B
    __shared__ float s_bias[128];

    init_phase(x, Wih0, Whh0, Wih1, Whh1);
    gridbar();

    // ping-pong: timestep t writes cur = buf[t&1], reads prev = buf[!(t&1)]
    for (int t = 0; t < TENC; t++) {
        float* cur  = (t & 1) ? g_hB : g_hA;
        float* prev = (t & 1) ? g_hA : g_hB;
        phase_layer(dyn, s_bias,
                    x + (size_t)t * ID, (size_t)TENC * ID, 128, prev, 1024,
                    g_rWih0, 128, 128, g_rWhh0, 512,
                    bih0, bhh0, g_c0, cur, 640);
        gridbar();
        phase_layer(dyn, s_bias,
                    cur, 1024, 512, prev + 512, 1024,
                    g_rWih1, 512, 512, g_rWhh1, 512,
                    bih1, bhh1, g_c1, cur + 512, 1024);
        gridbar();
    }

    for (int t = 0; t < TDEC; t++) {
        float* cur  = (t & 1) ? g_hB : g_hA;   // TENC even: parity continues
        float* prev = (t & 1) ? g_hA : g_hB;
        phase_layer(dyn, s_bias,
                    g_din, ID, 128, prev, 1024,
                    g_rWih0, 128, 128, g_rWhh0, 512,
                    bih0, bhh0, g_c0, cur, 640);
        gridbar();
        phase_layer(dyn, s_bias,
                    cur, 1024, 512, prev + 512, 1024,
                    g_rWih1, 512, 512, g_rWhh1, 512,
                    bih1, bhh1, g_c1, cur + 512, 1024);
        gridbar();
        fc_phase(dyn, cur, fcw, fcb, out, t);
        gridbar();
    }
}

// ---------------- entry ------------------------------------------------------
extern "C" void kernel_launch(void* const* d_in, const int* in_sizes, int n_in,
                              void* d_out, int out_size)
{
    const int smem = NST * STB;          // 110592
    cudaFuncSetAttribute(lstm_persistent,
                         cudaFuncAttributeMaxDynamicSharedMemorySize, smem);
    lstm_persistent<<<NBLK, NTHR, smem>>>(
        (const float*)d_in[0],
        (const float*)d_in[1], (const float*)d_in[2],
        (const float*)d_in[3], (const float*)d_in[4],
        (const float*)d_in[5], (const float*)d_in[6],
        (const float*)d_in[7], (const float*)d_in[8],
        (const float*)d_in[9], (const float*)d_in[10],
        (float*)d_out);
}

// round 11
// speedup vs baseline: 1.2896x; 1.0403x over previous
#include <cuda_runtime.h>
#include <math.h>
#include <cstdint>

#define BD   1024
#define HD   512
#define TENC 384
#define TDEC 128
#define ID   128
#define NBLK 128
#define NTHR 384           // 8 consumer warps + 4 producer warps

#define ROWB 144           // smem row stride bytes (32 floats + 16B pad)
#define TILEB (128 * ROWB) // 18432 per operand tile
#define STB  (2 * TILEB)   // 36864 per stage (A + B)
#define NST  3

// named barrier ids: FULL[st] = 1+st, EMPTY[st] = 4+st
#define BAR_CNT 384

// ---------------- static device scratch ------------------------------------
__device__ __align__(16) float g_hA[BD * 1024];   // ping-pong [h0|h1]
__device__ __align__(16) float g_hB[BD * 1024];
__device__ __align__(16) float g_c0 [BD * HD];
__device__ __align__(16) float g_c1 [BD * HD];
__device__ __align__(16) float g_din[BD * ID];
__device__ __align__(16) float g_rWih0[2048 * 128];
__device__ __align__(16) float g_rWhh0[2048 * 512];
__device__ __align__(16) float g_rWih1[2048 * 512];
__device__ __align__(16) float g_rWhh1[2048 * 512];
__device__ unsigned          g_bar_cnt;
__device__ volatile unsigned g_bar_gen;

// ---------------- helpers --------------------------------------------------
__device__ __forceinline__ uint32_t smem_u32(const void* p) {
    uint32_t a;
    asm("{ .reg .u64 t; cvta.to.shared.u64 t, %1; cvt.u32.u64 %0, t; }"
        : "=r"(a) : "l"(p));
    return a;
}
__device__ __forceinline__ float f2tf(float f) {
    unsigned u;
    asm("cvt.rna.tf32.f32 %0, %1;" : "=r"(u) : "f"(f));
    return __uint_as_float(u);
}
__device__ __forceinline__ float sigf(float x) {
    return __fdividef(1.f, 1.f + __expf(-x));
}
__device__ __forceinline__ float tanh_(float x) {
    float e = __expf(-2.f * fabsf(x));
    float t = __fdividef(1.f - e, 1.f + e);
    return copysignf(t, x);
}
__device__ __forceinline__ void cp16(uint32_t dst, const float* src) {
    asm volatile("cp.async.cg.shared.global [%0], [%1], 16;"
                 :: "r"(dst), "l"(src) : "memory");
}
__device__ __forceinline__ void mma8(float* c, uint32_t a0, uint32_t a1,
                                     uint32_t a2, uint32_t a3,
                                     uint32_t b0, uint32_t b1) {
    asm volatile("mma.sync.aligned.m16n8k8.row.col.f32.tf32.tf32.f32 "
                 "{%0,%1,%2,%3}, {%4,%5,%6,%7}, {%8,%9}, {%0,%1,%2,%3};"
                 : "+f"(c[0]), "+f"(c[1]), "+f"(c[2]), "+f"(c[3])
                 : "r"(a0), "r"(a1), "r"(a2), "r"(a3), "r"(b0), "r"(b1));
}
#define LDSM4(r, a)                                                          \
    asm volatile("ldmatrix.sync.aligned.m8n8.x4.shared.b16 {%0,%1,%2,%3}, [%4];" \
        : "=r"((r)[0]), "=r"((r)[1]), "=r"((r)[2]), "=r"((r)[3]) : "r"(a))

__device__ __forceinline__ float4 ldcg4(const float* p) {
    float4 v;
    asm volatile("ld.global.cg.v4.f32 {%0,%1,%2,%3}, [%4];"
                 : "=f"(v.x), "=f"(v.y), "=f"(v.z), "=f"(v.w) : "l"(p));
    return v;
}
__device__ __forceinline__ void bar_sync(int id) {
    asm volatile("bar.sync %0, %1;" :: "r"(id), "n"(BAR_CNT) : "memory");
}
__device__ __forceinline__ void bar_arrive(int id) {
    asm volatile("bar.arrive %0, %1;" :: "r"(id), "n"(BAR_CNT) : "memory");
}

// ---------------- grid barrier ---------------------------------------------
__device__ __forceinline__ void gridbar() {
    __syncthreads();
    if (threadIdx.x == 0) {
        unsigned gen = g_bar_gen;
        __threadfence();
        if (atomicAdd(&g_bar_cnt, 1u) == NBLK - 1u) {
            g_bar_cnt = 0u;
            __threadfence();
            g_bar_gen = gen + 1u;
        } else {
            while (g_bar_gen == gen) { __nanosleep(32); }
        }
        __threadfence();
    }
    __syncthreads();
}

// ---------------- init ------------------------------------------------------
__device__ void init_phase(const float* __restrict__ x,
                           const float* __restrict__ Wih0,
                           const float* __restrict__ Whh0,
                           const float* __restrict__ Wih1,
                           const float* __restrict__ Whh1)
{
    const int g = blockIdx.x * NTHR + threadIdx.x;
    const int GT = NBLK * NTHR;
    for (int i = g; i < BD * 1024; i += GT) { g_hA[i] = 0.f; g_hB[i] = 0.f; }
    for (int i = g; i < BD * HD; i += GT)   { g_c0[i] = 0.f; g_c1[i] = 0.f; }
    for (int i = g; i < BD * ID; i += GT) {
        int b = i >> 7, col = i & 127;
        g_din[i] = f2tf(x[(size_t)b * (TENC * ID) + (size_t)(TENC - 1) * ID + col]);
    }
    for (int i = g; i < 2048 * 128; i += GT) g_rWih0[i] = f2tf(Wih0[i]);
    for (int i = g; i < 2048 * 512; i += GT) {
        g_rWhh0[i] = f2tf(Whh0[i]);
        g_rWih1[i] = f2tf(Wih1[i]);
        g_rWhh1[i] = f2tf(Whh1[i]);
    }
}

// ---------------- fused GEMM + gates phase (warp-specialized) ---------------
// CTA tile: 128 batch rows x 128 gate cols ({i,f,g,o} x 32 j at j0).
// Warps 0-7: consumers (2x4 grid, 64m x 32n each). Warps 8-11: producers.
__device__ void phase_layer(char* smem, float* sbias,
                            const float* A1, size_t lda1, int KA1,
                            const float* A2, int lda2,
                            const float* W1, int ldw1, int KW1,
                            const float* W2, int ldw2,
                            const float* bih, const float* bhh,
                            float* cbuf, float* hdst, int KT)
{
    const int tid  = threadIdx.x;
    const int warp = tid >> 5, lane = tid & 31;
    const int m0 = (blockIdx.x >> 4) * 128;
    const int j0 = (blockIdx.x & 15) * 32;
    const int nch = KT >> 5;             // #k32 chunks (20 or 32)

    if (tid < 128) {
        int n = (tid >> 5) * 512 + j0 + (tid & 31);
        sbias[tid] = bih[n] + bhh[n];
    }

    const uint32_t sA = smem_u32(smem);
    const uint32_t sB = sA + (uint32_t)TILEB;

    if (warp >= 8) {
        // ================= producer path =================
        const int p = tid - 256;                   // 0..127
        const uint32_t dA = sA + (uint32_t)p * ROWB;
        const uint32_t dB = sB + (uint32_t)p * ROWB;
        const int nrow = (p >> 5) * 512 + j0 + (p & 31);
        const float* a1r = A1 + (size_t)(m0 + p) * lda1;
        const float* a2r = A2 + (size_t)(m0 + p) * lda2 - KA1;
        const float* w1r = W1 + (size_t)nrow * ldw1;
        const float* w2r = W2 + (size_t)nrow * ldw2 - KW1;

        for (int ch = 0; ch < nch; ch++) {
            int st = ch - (ch / NST) * NST;
            int k0 = ch * 32;
            bar_sync(4 + st);                      // stage free?
            const float* srcA = (k0 < KA1) ? a1r + k0 : a2r + k0;
            const float* srcB = (k0 < KW1) ? w1r + k0 : w2r + k0;
            uint32_t da = dA + (uint32_t)st * STB;
            uint32_t db = dB + (uint32_t)st * STB;
#pragma unroll
            for (int q = 0; q < 8; q++) {
                cp16(da + q * 16u, srcA + q * 4);
                cp16(db + q * 16u, srcB + q * 4);
            }
            asm volatile("cp.async.commit_group;" ::: "memory");
            if (ch > 0) {
                asm volatile("cp.async.wait_group 1;" ::: "memory");
                int pst = (ch - 1) - ((ch - 1) / NST) * NST;
                bar_arrive(1 + pst);               // stage ch-1 full
            }
        }
        asm volatile("cp.async.wait_group 0;" ::: "memory");
        {
            int pst = (nch - 1) - ((nch - 1) / NST) * NST;
            bar_arrive(1 + pst);
        }
    } else {
        // ================= consumer path =================
        const int wm = (warp >> 2) * 64;
        const int wn = (warp & 3) * 32;
        const uint32_t offA = sA + (uint32_t)((((lane >> 3) & 1) * 8 + (lane & 7)) * ROWB)
                                 + (uint32_t)((lane >> 4) * 16) + (uint32_t)wm * ROWB;
        const uint32_t offB = sB + (uint32_t)((lane & 7) * ROWB)
                                 + (uint32_t)((lane >> 3) * 16) + (uint32_t)wn * ROWB;

        float acc[4][4][4];
#pragma unroll
        for (int mi = 0; mi < 4; mi++)
#pragma unroll
            for (int ni = 0; ni < 4; ni++)
#pragma unroll
                for (int r = 0; r < 4; r++) acc[mi][ni][r] = 0.f;

        for (int ch = 0; ch < nch; ch++) {
            int st = ch - (ch / NST) * NST;
            bar_sync(1 + st);                      // wait stage full
            const uint32_t so = (uint32_t)st * STB;
#pragma unroll
            for (int h = 0; h < 2; h++) {          // two k16 halves
                uint32_t fb[4][4];
#pragma unroll
                for (int ni = 0; ni < 4; ni++)
                    LDSM4(fb[ni], offB + so + (uint32_t)(ni * 8 * ROWB) + (uint32_t)(h * 64));
#pragma unroll
                for (int mi = 0; mi < 4; mi++) {
                    uint32_t fa0[4], fa1[4];
                    LDSM4(fa0, offA + so + (uint32_t)(mi * 16 * ROWB) + (uint32_t)(h * 64));
                    LDSM4(fa1, offA + so + (uint32_t)(mi * 16 * ROWB) + (uint32_t)(h * 64) + 32u);
#pragma unroll
                    for (int ni = 0; ni < 4; ni++) {
                        mma8(acc[mi][ni], fa0[0], fa0[1], fa0[2], fa0[3], fb[ni][0], fb[ni][1]);
                        mma8(acc[mi][ni], fa1[0], fa1[1], fa1[2], fa1[3], fb[ni][2], fb[ni][3]);
                    }
                }
            }
            bar_arrive(4 + st);                    // stage consumed
        }

        // epilogue part 1: accs -> smem z-buffer (after full-CTA sync below)
        __syncthreads();                           // producers join here
        {
            const int gid = lane >> 2, t4 = lane & 3;
#pragma unroll
            for (int mi = 0; mi < 4; mi++) {
                int r0 = wm + mi * 16 + gid;
#pragma unroll
                for (int ni = 0; ni < 4; ni++) {
                    int c = wn + ni * 8 + t4 * 2;
                    float* zb = (float*)smem;
                    *(float2*)&zb[(size_t)r0 * 132 + c]       = make_float2(acc[mi][ni][0], acc[mi][ni][1]);
                    *(float2*)&zb[(size_t)(r0 + 8) * 132 + c] = make_float2(acc[mi][ni][2], acc[mi][ni][3]);
                }
            }
        }
    }

    if (warp >= 8) __syncthreads();                // producers' side of the sync
    __syncthreads();                               // zb visible to all

    if (tid < 256) {
        float* zb = (float*)smem;
        const int row_ = tid >> 1;                 // 0..127
        const int jh   = (tid & 1) * 16;           // 0 or 16
        const int m    = m0 + row_;
        const float* zr = zb + (size_t)row_ * 132;
        float* cp_ = cbuf + (size_t)m * HD + j0 + jh;
        float* hp_ = hdst + (size_t)m * 1024 + j0 + jh;
#pragma unroll
        for (int jj = 0; jj < 16; jj++) {
            int j = jh + jj;
            float zi = zr[j]      + sbias[j];
            float zf = zr[32 + j] + sbias[32 + j];
            float zg = zr[64 + j] + sbias[64 + j];
            float zo = zr[96 + j] + sbias[96 + j];
            float c = sigf(zf) * cp_[jj] + sigf(zi) * tanh_(zg);
            cp_[jj] = c;
            hp_[jj] = f2tf(sigf(zo) * tanh_(c));
        }
    }
    __syncthreads();
}

// ---------------- fc phase (decoder projection) ------------------------------
__device__ void fc_phase(char* smem, const float* __restrict__ hcur,
                         const float* __restrict__ fcw,
                         const float* __restrict__ fcb,
                         float* __restrict__ out, int t)
{
    const int m0 = (blockIdx.x >> 2) * 32;     // 32 batch rows
    const int c0 = (blockIdx.x & 3) * 32;      // 32 out cols
    const int tid = threadIdx.x;
    float* hs = (float*)smem;                  // 32 x 136 floats

    float a0 = 0.f, a1 = 0.f, a2 = 0.f, a3 = 0.f;
    const int r  = (tid & 255) >> 3;
    const int cq = c0 + (tid & 7) * 4;

    for (int kc = 0; kc < HD; kc += 128) {
        __syncthreads();
        if (tid < 256) {   // load h1 tile 32 x 128 (cross-CTA: bypass L1)
            int rr = tid >> 3, u = (tid & 7) * 16;
            const float* src = hcur + (size_t)(m0 + rr) * 1024 + 512 + kc + u;
            float* dst = hs + (size_t)rr * 136 + u;
#pragma unroll
            for (int q = 0; q < 4; q++)
                *(float4*)(dst + q * 4) = ldcg4(src + q * 4);
        }
        __syncthreads();
        if (tid < 256) {
            const float* hr = hs + (size_t)r * 136;
            const float4* w0 = (const float4*)(fcw + (size_t)(cq + 0) * HD + kc);
            const float4* w1 = (const float4*)(fcw + (size_t)(cq + 1) * HD + kc);
            const float4* w2 = (const float4*)(fcw + (size_t)(cq + 2) * HD + kc);
            const float4* w3 = (const float4*)(fcw + (size_t)(cq + 3) * HD + kc);
#pragma unroll 8
            for (int k4 = 0; k4 < 32; k4++) {
                float4 h4 = *(const float4*)(hr + k4 * 4);
                float4 v0 = __ldg(w0 + k4), v1 = __ldg(w1 + k4);
                float4 v2 = __ldg(w2 + k4), v3 = __ldg(w3 + k4);
                a0 += h4.x * v0.x + h4.y * v0.y + h4.z * v0.z + h4.w * v0.w;
                a1 += h4.x * v1.x + h4.y * v1.y + h4.z * v1.z + h4.w * v1.w;
                a2 += h4.x * v2.x + h4.y * v2.y + h4.z * v2.z + h4.w * v2.w;
                a3 += h4.x * v3.x + h4.y * v3.y + h4.z * v3.z + h4.w * v3.w;
            }
        }
    }
    if (tid < 256) {
        float4 res = make_float4(a0 + fcb[cq], a1 + fcb[cq + 1],
                                 a2 + fcb[cq + 2], a3 + fcb[cq + 3]);
        *(float4*)(out + (size_t)(m0 + r) * (TDEC * ID) + (size_t)t * ID + cq) = res;
        float4 dv = make_float4(f2tf(res.x), f2tf(res.y), f2tf(res.z), f2tf(res.w));
        *(float4*)(g_din + (size_t)(m0 + r) * ID + cq) = dv;
    }
    __syncthreads();
}

// ---------------- persistent kernel -----------------------------------------
__global__ void __launch_bounds__(NTHR, 1)
lstm_persistent(const float* __restrict__ x,
                const float* __restrict__ Wih0, const float* __restrict__ Whh0,
                const float* __restrict__ bih0, const float* __restrict__ bhh0,
                const float* __restrict__ Wih1, const float* __restrict__ Whh1,
                const float* __restrict__ bih1, const float* __restrict__ bhh1,
                const float* __restrict__ fcw,  const float* __restrict__ fcb,
                float* __restrict__ out)
{
    extern __shared__ char dyn[];        // NST * STB = 110592 B
    __shared__ float s_bias[128];

    // prime EMPTY barriers: one consumer-side arrival round per stage
    if (threadIdx.x < 256) {
        bar_arrive(4); bar_arrive(5); bar_arrive(6);
    }

    init_phase(x, Wih0, Whh0, Wih1, Whh1);
    gridbar();

    for (int t = 0; t < TENC; t++) {
        float* cur  = (t & 1) ? g_hB : g_hA;
        float* prev = (t & 1) ? g_hA : g_hB;
        phase_layer(dyn, s_bias,
                    x + (size_t)t * ID, (size_t)TENC * ID, 128, prev, 1024,
                    g_rWih0, 128, 128, g_rWhh0, 512,
                    bih0, bhh0, g_c0, cur, 640);
        gridbar();
        phase_layer(dyn, s_bias,
                    cur, 1024, 512, prev + 512, 1024,
                    g_rWih1, 512, 512, g_rWhh1, 512,
                    bih1, bhh1, g_c1, cur + 512, 1024);
        gridbar();
    }

    for (int t = 0; t < TDEC; t++) {
        float* cur  = (t & 1) ? g_hB : g_hA;
        float* prev = (t & 1) ? g_hA : g_hB;
        phase_layer(dyn, s_bias,
                    g_din, ID, 128, prev, 1024,
                    g_rWih0, 128, 128, g_rWhh0, 512,
                    bih0, bhh0, g_c0, cur, 640);
        gridbar();
        phase_layer(dyn, s_bias,
                    cur, 1024, 512, prev + 512, 1024,
                    g_rWih1, 512, 512, g_rWhh1, 512,
                    bih1, bhh1, g_c1, cur + 512, 1024);
        gridbar();
        fc_phase(dyn, cur, fcw, fcb, out, t);
        gridbar();
    }
}

// ---------------- entry ------------------------------------------------------
extern "C" void kernel_launch(void* const* d_in, const int* in_sizes, int n_in,
                              void* d_out, int out_size)
{
    const int smem = NST * STB;          // 110592
    cudaFuncSetAttribute(lstm_persistent,
                         cudaFuncAttributeMaxDynamicSharedMemorySize, smem);
    lstm_persistent<<<NBLK, NTHR, smem>>>(
        (const float*)d_in[0],
        (const float*)d_in[1], (const float*)d_in[2],
        (const float*)d_in[3], (const float*)d_in[4],
        (const float*)d_in[5], (const float*)d_in[6],
        (const float*)d_in[7], (const float*)d_in[8],
        (const float*)d_in[9], (const float*)d_in[10],
        (float*)d_out);
}

// round 12
// speedup vs baseline: 1.8412x; 1.4277x over previous
#include <cuda_runtime.h>
#include <cuda_bf16.h>
#include <math.h>
#include <cstdint>

#define BD   1024
#define HD   512
#define TENC 384
#define TDEC 128
#define ID   128
#define NBLK 128
#define NTHR 384           // 8 consumer warps + 4 producer warps

#define ROWB 144           // smem row stride bytes (64 bf16 = 128B + 16B pad)
#define TILEB (128 * ROWB) // 18432 per operand tile
#define STB  (2 * TILEB)   // 36864 per stage (A + B)
#define NST  3

#define BAR_CNT 384        // named barriers: FULL[st]=1+st, EMPTY[st]=4+st

// ---------------- static device scratch ------------------------------------
__device__ __align__(16) __nv_bfloat16 g_hA[BD * 1024];   // ping-pong [h0|h1]
__device__ __align__(16) __nv_bfloat16 g_hB[BD * 1024];
__device__ __align__(16) float         g_h1f[BD * HD];    // fp32 h1 for fc
__device__ __align__(16) float g_c0 [BD * HD];
__device__ __align__(16) float g_c1 [BD * HD];
__device__ __align__(16) __nv_bfloat16 g_din[BD * ID];
__device__ __align__(16) __nv_bfloat16 g_xb [BD * TENC * ID];   // bf16 x copy
__device__ __align__(16) __nv_bfloat16 g_rWih0[2048 * 128];
__device__ __align__(16) __nv_bfloat16 g_rWhh0[2048 * 512];
__device__ __align__(16) __nv_bfloat16 g_rWih1[2048 * 512];
__device__ __align__(16) __nv_bfloat16 g_rWhh1[2048 * 512];
__device__ unsigned          g_bar_cnt;
__device__ volatile unsigned g_bar_gen;

// ---------------- helpers --------------------------------------------------
__device__ __forceinline__ uint32_t smem_u32(const void* p) {
    uint32_t a;
    asm("{ .reg .u64 t; cvta.to.shared.u64 t, %1; cvt.u32.u64 %0, t; }"
        : "=r"(a) : "l"(p));
    return a;
}
__device__ __forceinline__ float sigf(float x) {
    return __fdividef(1.f, 1.f + __expf(-x));
}
__device__ __forceinline__ float tanh_(float x) {
    float e = __expf(-2.f * fabsf(x));
    float t = __fdividef(1.f - e, 1.f + e);
    return copysignf(t, x);
}
__device__ __forceinline__ void cp16(uint32_t dst, const void* src) {
    asm volatile("cp.async.cg.shared.global [%0], [%1], 16;"
                 :: "r"(dst), "l"(src) : "memory");
}
__device__ __forceinline__ void mma16(float* c, uint32_t a0, uint32_t a1,
                                      uint32_t a2, uint32_t a3,
                                      uint32_t b0, uint32_t b1) {
    asm volatile("mma.sync.aligned.m16n8k16.row.col.f32.bf16.bf16.f32 "
                 "{%0,%1,%2,%3}, {%4,%5,%6,%7}, {%8,%9}, {%0,%1,%2,%3};"
                 : "+f"(c[0]), "+f"(c[1]), "+f"(c[2]), "+f"(c[3])
                 : "r"(a0), "r"(a1), "r"(a2), "r"(a3), "r"(b0), "r"(b1));
}
#define LDSM4(r, a)                                                          \
    asm volatile("ldmatrix.sync.aligned.m8n8.x4.shared.b16 {%0,%1,%2,%3}, [%4];" \
        : "=r"((r)[0]), "=r"((r)[1]), "=r"((r)[2]), "=r"((r)[3]) : "r"(a))

__device__ __forceinline__ float4 ldcg4(const float* p) {
    float4 v;
    asm volatile("ld.global.cg.v4.f32 {%0,%1,%2,%3}, [%4];"
                 : "=f"(v.x), "=f"(v.y), "=f"(v.z), "=f"(v.w) : "l"(p));
    return v;
}
__device__ __forceinline__ void bar_sync(int id) {
    asm volatile("bar.sync %0, %1;" :: "r"(id), "n"(BAR_CNT) : "memory");
}
__device__ __forceinline__ void bar_arrive(int id) {
    asm volatile("bar.arrive %0, %1;" :: "r"(id), "n"(BAR_CNT) : "memory");
}

// ---------------- grid barrier ---------------------------------------------
__device__ __forceinline__ void gridbar() {
    __syncthreads();
    if (threadIdx.x == 0) {
        unsigned gen = g_bar_gen;
        __threadfence();
        if (atomicAdd(&g_bar_cnt, 1u) == NBLK - 1u) {
            g_bar_cnt = 0u;
            __threadfence();
            g_bar_gen = gen + 1u;
        } else {
            while (g_bar_gen == gen) { __nanosleep(32); }
        }
        __threadfence();
    }
    __syncthreads();
}

// ---------------- init: bf16 conversions + state zero -----------------------
__device__ __forceinline__ uint32_t packbf(float a, float b) {
    __nv_bfloat162 v = __floats2bfloat162_rn(a, b);
    return *(uint32_t*)&v;
}
__device__ void cvt_arr(const float* __restrict__ src, __nv_bfloat16* dst,
                        int n, int g, int GT)
{
    const float4* s4 = (const float4*)src;
    uint2* d4 = (uint2*)dst;
    for (int i = g; i < n / 4; i += GT) {
        float4 v = s4[i];
        d4[i] = make_uint2(packbf(v.x, v.y), packbf(v.z, v.w));
    }
}
__device__ void init_phase(const float* __restrict__ x,
                           const float* __restrict__ Wih0,
                           const float* __restrict__ Whh0,
                           const float* __restrict__ Wih1,
                           const float* __restrict__ Whh1)
{
    const int g = blockIdx.x * NTHR + threadIdx.x;
    const int GT = NBLK * NTHR;
    uint32_t* hA = (uint32_t*)g_hA;
    uint32_t* hB = (uint32_t*)g_hB;
    for (int i = g; i < BD * 1024 / 2; i += GT) { hA[i] = 0u; hB[i] = 0u; }
    for (int i = g; i < BD * HD; i += GT) { g_c0[i] = 0.f; g_c1[i] = 0.f; }
    for (int i = g; i < BD * ID; i += GT) {
        int b = i >> 7, col = i & 127;
        g_din[i] = __float2bfloat16(
            x[(size_t)b * (TENC * ID) + (size_t)(TENC - 1) * ID + col]);
    }
    cvt_arr(x,    g_xb,    BD * TENC * ID, g, GT);
    cvt_arr(Wih0, g_rWih0, 2048 * 128, g, GT);
    cvt_arr(Whh0, g_rWhh0, 2048 * 512, g, GT);
    cvt_arr(Wih1, g_rWih1, 2048 * 512, g, GT);
    cvt_arr(Whh1, g_rWhh1, 2048 * 512, g, GT);
}

// ---------------- fused GEMM + gates phase (warp-specialized, bf16) ---------
// CTA tile: 128 batch rows x 128 gate cols ({i,f,g,o} x 32 j at j0).
// Warps 0-7: consumers (2x4 grid, 64m x 32n). Warps 8-11: producers.
// k chunks of 64 bf16 elements (128 B/row).
__device__ void phase_layer(char* smem, float* sbias,
                            const __nv_bfloat16* A1, size_t lda1, int KA1,
                            const __nv_bfloat16* A2, int lda2,
                            const __nv_bfloat16* W1, int ldw1, int KW1,
                            const __nv_bfloat16* W2, int ldw2,
                            const float* bih, const float* bhh,
                            float* cbuf, __nv_bfloat16* hdst, float* hfp,
                            int KT)
{
    const int tid  = threadIdx.x;
    const int warp = tid >> 5, lane = tid & 31;
    const int m0 = (blockIdx.x >> 4) * 128;
    const int j0 = (blockIdx.x & 15) * 32;
    const int nch = KT >> 6;             // #k64 chunks (10 or 16)

    if (tid < 128) {
        int n = (tid >> 5) * 512 + j0 + (tid & 31);
        sbias[tid] = bih[n] + bhh[n];
    }

    const uint32_t sA = smem_u32(smem);
    const uint32_t sB = sA + (uint32_t)TILEB;

    if (warp >= 8) {
        // ================= producer path =================
        const int p = tid - 256;                   // 0..127
        const uint32_t dA = sA + (uint32_t)p * ROWB;
        const uint32_t dB = sB + (uint32_t)p * ROWB;
        const int nrow = (p >> 5) * 512 + j0 + (p & 31);
        const __nv_bfloat16* a1r = A1 + (size_t)(m0 + p) * lda1;
        const __nv_bfloat16* a2r = A2 + (size_t)(m0 + p) * lda2 - KA1;
        const __nv_bfloat16* w1r = W1 + (size_t)nrow * ldw1;
        const __nv_bfloat16* w2r = W2 + (size_t)nrow * ldw2 - KW1;

        for (int ch = 0; ch < nch; ch++) {
            int st = ch - (ch / NST) * NST;
            int k0 = ch * 64;
            bar_sync(4 + st);                      // stage free?
            const __nv_bfloat16* srcA = (k0 < KA1) ? a1r + k0 : a2r + k0;
            const __nv_bfloat16* srcB = (k0 < KW1) ? w1r + k0 : w2r + k0;
            uint32_t da = dA + (uint32_t)st * STB;
            uint32_t db = dB + (uint32_t)st * STB;
#pragma unroll
            for (int q = 0; q < 8; q++) {          // 8 x 16B = 128B per row
                cp16(da + q * 16u, srcA + q * 8);
                cp16(db + q * 16u, srcB + q * 8);
            }
            asm volatile("cp.async.commit_group;" ::: "memory");
            if (ch > 0) {
                asm volatile("cp.async.wait_group 1;" ::: "memory");
                int pst = (ch - 1) - ((ch - 1) / NST) * NST;
                bar_arrive(1 + pst);               // stage ch-1 full
            }
        }
        asm volatile("cp.async.wait_group 0;" ::: "memory");
        {
            int pst = (nch - 1) - ((nch - 1) / NST) * NST;
            bar_arrive(1 + pst);
        }
    } else {
        // ================= consumer path =================
        const int wm = (warp >> 2) * 64;
        const int wn = (warp & 3) * 32;
        // x4 ldmatrix addr: lane -> row (l&15), k-halftile (l>>4)*16B
        const uint32_t offA = sA + (uint32_t)((lane & 15) * ROWB)
                                 + (uint32_t)((lane >> 4) * 16)
                                 + (uint32_t)wm * ROWB;
        const uint32_t offB = sB + (uint32_t)((lane & 15) * ROWB)
                                 + (uint32_t)((lane >> 4) * 16)
                                 + (uint32_t)wn * ROWB;

        float acc[4][4][4];
#pragma unroll
        for (int mi = 0; mi < 4; mi++)
#pragma unroll
            for (int ni = 0; ni < 4; ni++)
#pragma unroll
                for (int r = 0; r < 4; r++) acc[mi][ni][r] = 0.f;

        for (int ch = 0; ch < nch; ch++) {
            int st = ch - (ch / NST) * NST;
            bar_sync(1 + st);                      // wait stage full
            const uint32_t so = (uint32_t)st * STB;
#pragma unroll
            for (int ks = 0; ks < 4; ks++) {       // four k16 steps of k64
                const uint32_t ko = (uint32_t)(ks * 32);   // 16 els * 2B
                uint32_t fb0[4], fb1[4];
                LDSM4(fb0, offB + so + ko);                      // n 0-15
                LDSM4(fb1, offB + so + 16u * ROWB + ko);         // n 16-31
#pragma unroll
                for (int mi = 0; mi < 4; mi++) {
                    uint32_t fa[4];
                    LDSM4(fa, offA + so + (uint32_t)(mi * 16 * ROWB) + ko);
                    mma16(acc[mi][0], fa[0], fa[1], fa[2], fa[3], fb0[0], fb0[2]);
                    mma16(acc[mi][1], fa[0], fa[1], fa[2], fa[3], fb0[1], fb0[3]);
                    mma16(acc[mi][2], fa[0], fa[1], fa[2], fa[3], fb1[0], fb1[2]);
                    mma16(acc[mi][3], fa[0], fa[1], fa[2], fa[3], fb1[1], fb1[3]);
                }
            }
            bar_arrive(4 + st);                    // stage consumed
        }

        __syncthreads();                           // pair with producers below
        {
            const int gid = lane >> 2, t4 = lane & 3;
            float* zb = (float*)smem;
#pragma unroll
            for (int mi = 0; mi < 4; mi++) {
                int r0 = wm + mi * 16 + gid;
#pragma unroll
                for (int ni = 0; ni < 4; ni++) {
                    int c = wn + ni * 8 + t4 * 2;
                    *(float2*)&zb[(size_t)r0 * 132 + c]       = make_float2(acc[mi][ni][0], acc[mi][ni][1]);
                    *(float2*)&zb[(size_t)(r0 + 8) * 132 + c] = make_float2(acc[mi][ni][2], acc[mi][ni][3]);
                }
            }
        }
    }

    if (warp >= 8) __syncthreads();                // producers' pairing sync
    __syncthreads();                               // zb visible to all

    if (tid < 256) {
        float* zb = (float*)smem;
        const int row_ = tid >> 1;                 // 0..127
        const int jh   = (tid & 1) * 16;           // 0 or 16
        const int m    = m0 + row_;
        const float* zr = zb + (size_t)row_ * 132;
        float* cp_ = cbuf + (size_t)m * HD + j0 + jh;
        __nv_bfloat16* hp_ = hdst + (size_t)m * 1024 + j0 + jh;
        float* hf_ = hfp ? hfp + (size_t)m * HD + j0 + jh : nullptr;
#pragma unroll
        for (int jj = 0; jj < 16; jj++) {
            int j = jh + jj;
            float zi = zr[j]      + sbias[j];
            float zf = zr[32 + j] + sbias[32 + j];
            float zg = zr[64 + j] + sbias[64 + j];
            float zo = zr[96 + j] + sbias[96 + j];
            float c = sigf(zf) * cp_[jj] + sigf(zi) * tanh_(zg);
            cp_[jj] = c;
            float h = sigf(zo) * tanh_(c);
            hp_[jj] = __float2bfloat16(h);
            if (hf_) hf_[jj] = h;
        }
    }
    __syncthreads();
}

// ---------------- fc phase (decoder projection, fp32) ------------------------
__device__ void fc_phase(char* smem,
                         const float* __restrict__ fcw,
                         const float* __restrict__ fcb,
                         float* __restrict__ out, int t)
{
    const int m0 = (blockIdx.x >> 2) * 32;     // 32 batch rows
    const int c0 = (blockIdx.x & 3) * 32;      // 32 out cols
    const int tid = threadIdx.x;
    float* hs = (float*)smem;                  // 32 x 136 floats

    float a0 = 0.f, a1 = 0.f, a2 = 0.f, a3 = 0.f;
    const int r  = (tid & 255) >> 3;
    const int cq = c0 + (tid & 7) * 4;

    for (int kc = 0; kc < HD; kc += 128) {
        __syncthreads();
        if (tid < 256) {   // load fp32 h1 tile 32 x 128 (cross-CTA: bypass L1)
            int rr = tid >> 3, u = (tid & 7) * 16;
            const float* src = g_h1f + (size_t)(m0 + rr) * HD + kc + u;
            float* dst = hs + (size_t)rr * 136 + u;
#pragma unroll
            for (int q = 0; q < 4; q++)
                *(float4*)(dst + q * 4) = ldcg4(src + q * 4);
        }
        __syncthreads();
        if (tid < 256) {
            const float* hr = hs + (size_t)r * 136;
            const float4* w0 = (const float4*)(fcw + (size_t)(cq + 0) * HD + kc);
            const float4* w1 = (const float4*)(fcw + (size_t)(cq + 1) * HD + kc);
            const float4* w2 = (const float4*)(fcw + (size_t)(cq + 2) * HD + kc);
            const float4* w3 = (const float4*)(fcw + (size_t)(cq + 3) * HD + kc);
#pragma unroll 8
            for (int k4 = 0; k4 < 32; k4++) {
                float4 h4 = *(const float4*)(hr + k4 * 4);
                float4 v0 = __ldg(w0 + k4), v1 = __ldg(w1 + k4);
                float4 v2 = __ldg(w2 + k4), v3 = __ldg(w3 + k4);
                a0 += h4.x * v0.x + h4.y * v0.y + h4.z * v0.z + h4.w * v0.w;
                a1 += h4.x * v1.x + h4.y * v1.y + h4.z * v1.z + h4.w * v1.w;
                a2 += h4.x * v2.x + h4.y * v2.y + h4.z * v2.z + h4.w * v2.w;
                a3 += h4.x * v3.x + h4.y * v3.y + h4.z * v3.z + h4.w * v3.w;
            }
        }
    }
    if (tid < 256) {
        float4 res = make_float4(a0 + fcb[cq], a1 + fcb[cq + 1],
                                 a2 + fcb[cq + 2], a3 + fcb[cq + 3]);
        *(float4*)(out + (size_t)(m0 + r) * (TDEC * ID) + (size_t)t * ID + cq) = res;
        // decoder feedback in bf16
        __nv_bfloat16* dp = g_din + (size_t)(m0 + r) * ID + cq;
        uint2 dv = make_uint2(packbf(res.x, res.y), packbf(res.z, res.w));
        *(uint2*)dp = dv;
    }
    __syncthreads();
}

// ---------------- persistent kernel -----------------------------------------
__global__ void __launch_bounds__(NTHR, 1)
lstm_persistent(const float* __restrict__ x,
                const float* __restrict__ Wih0, const float* __restrict__ Whh0,
                const float* __restrict__ bih0, const float* __restrict__ bhh0,
                const float* __restrict__ Wih1, const float* __restrict__ Whh1,
                const float* __restrict__ bih1, const float* __restrict__ bhh1,
                const float* __restrict__ fcw,  const float* __restrict__ fcb,
                float* __restrict__ out)
{
    extern __shared__ char dyn[];        // NST * STB = 110592 B
    __shared__ float s_bias[128];

    // prime EMPTY barriers: one consumer-side arrival round per stage
    if (threadIdx.x < 256) {
        bar_arrive(4); bar_arrive(5); bar_arrive(6);
    }

    init_phase(x, Wih0, Whh0, Wih1, Whh1);
    gridbar();

    for (int t = 0; t < TENC; t++) {
        __nv_bfloat16* cur  = (t & 1) ? g_hB : g_hA;
        __nv_bfloat16* prev = (t & 1) ? g_hA : g_hB;
        phase_layer(dyn, s_bias,
                    g_xb + (size_t)t * ID, (size_t)TENC * ID, 128, prev, 1024,
                    g_rWih0, 128, 128, g_rWhh0, 512,
                    bih0, bhh0, g_c0, cur, nullptr, 640);
        gridbar();
        phase_layer(dyn, s_bias,
                    cur, 1024, 512, prev + 512, 1024,
                    g_rWih1, 512, 512, g_rWhh1, 512,
                    bih1, bhh1, g_c1, cur + 512, nullptr, 1024);
        gridbar();
    }

    for (int t = 0; t < TDEC; t++) {
        __nv_bfloat16* cur  = (t & 1) ? g_hB : g_hA;
        __nv_bfloat16* prev = (t & 1) ? g_hA : g_hB;
        phase_layer(dyn, s_bias,
                    g_din, ID, 128, prev, 1024,
                    g_rWih0, 128, 128, g_rWhh0, 512,
                    bih0, bhh0, g_c0, cur, nullptr, 640);
        gridbar();
        phase_layer(dyn, s_bias,
                    cur, 1024, 512, prev + 512, 1024,
                    g_rWih1, 512, 512, g_rWhh1, 512,
                    bih1, bhh1, g_c1, cur + 512, g_h1f, 1024);
        gridbar();
        fc_phase(dyn, fcw, fcb, out, t);
        gridbar();
    }
}

// ---------------- entry ------------------------------------------------------
extern "C" void kernel_launch(void* const* d_in, const int* in_sizes, int n_in,
                              void* d_out, int out_size)
{
    const int smem = NST * STB;          // 110592
    cudaFuncSetAttribute(lstm_persistent,
                         cudaFuncAttributeMaxDynamicSharedMemorySize, smem);
    lstm_persistent<<<NBLK, NTHR, smem>>>(
        (const float*)d_in[0],
        (const float*)d_in[1], (const float*)d_in[2],
        (const float*)d_in[3], (const float*)d_in[4],
        (const float*)d_in[5], (const float*)d_in[6],
        (const float*)d_in[7], (const float*)d_in[8],
        (const float*)d_in[9], (const float*)d_in[10],
        (float*)d_out);
}

// round 13
// speedup vs baseline: 1.8752x; 1.0185x over previous
#include <cuda_runtime.h>
#include <cuda_bf16.h>
#include <math.h>
#include <cstdint>

#define BD   1024
#define HD   512
#define TENC 384
#define TDEC 128
#define ID   128
#define NBLK 128
#define NTHR 384           // 8 consumer warps + 4 producer warps

#define ROWB 144           // smem row stride bytes (64 bf16 = 128B + 16B pad)
#define TILEB (128 * ROWB) // 18432 per operand tile
#define STB  (2 * TILEB)   // 36864 per stage (A + B)
#define NST  3

#define BAR_CNT 384        // named barriers: FULL[st]=1+st, EMPTY[st]=4+st

// ---------------- static device scratch ------------------------------------
__device__ __align__(16) __nv_bfloat16 g_hA[BD * 1024];   // ping-pong [h0|h1]
__device__ __align__(16) __nv_bfloat16 g_hB[BD * 1024];
__device__ __align__(16) float         g_h1f[BD * HD];    // fp32 h1 for fc
__device__ __align__(16) float g_c0 [BD * HD];
__device__ __align__(16) float g_c1 [BD * HD];
__device__ __align__(16) __nv_bfloat16 g_din[BD * ID];
__device__ __align__(16) __nv_bfloat16 g_xb [BD * TENC * ID];   // bf16 x copy
__device__ __align__(16) __nv_bfloat16 g_rWih0[2048 * 128];
__device__ __align__(16) __nv_bfloat16 g_rWhh0[2048 * 512];
__device__ __align__(16) __nv_bfloat16 g_rWih1[2048 * 512];
__device__ __align__(16) __nv_bfloat16 g_rWhh1[2048 * 512];
__device__ unsigned          g_bar_cnt;
__device__ volatile unsigned g_bar_gen;

// ---------------- helpers --------------------------------------------------
__device__ __forceinline__ uint32_t smem_u32(const void* p) {
    uint32_t a;
    asm("{ .reg .u64 t; cvta.to.shared.u64 t, %1; cvt.u32.u64 %0, t; }"
        : "=r"(a) : "l"(p));
    return a;
}
// HW tanh (sm_75+): single MUFU op
__device__ __forceinline__ float tanh_a(float x) {
    float r;
    asm("tanh.approx.f32 %0, %1;" : "=f"(r) : "f"(x));
    return r;
}
// sigmoid via HW tanh: 1 MUFU + 2 FMA-pipe ops
__device__ __forceinline__ float sig_a(float x) {
    return fmaf(0.5f, tanh_a(0.5f * x), 0.5f);
}
__device__ __forceinline__ void cp16(uint32_t dst, const void* src) {
    asm volatile("cp.async.cg.shared.global [%0], [%1], 16;"
                 :: "r"(dst), "l"(src) : "memory");
}
__device__ __forceinline__ void mma16(float* c, uint32_t a0, uint32_t a1,
                                      uint32_t a2, uint32_t a3,
                                      uint32_t b0, uint32_t b1) {
    asm volatile("mma.sync.aligned.m16n8k16.row.col.f32.bf16.bf16.f32 "
                 "{%0,%1,%2,%3}, {%4,%5,%6,%7}, {%8,%9}, {%0,%1,%2,%3};"
                 : "+f"(c[0]), "+f"(c[1]), "+f"(c[2]), "+f"(c[3])
                 : "r"(a0), "r"(a1), "r"(a2), "r"(a3), "r"(b0), "r"(b1));
}
#define LDSM4(r, a)                                                          \
    asm volatile("ldmatrix.sync.aligned.m8n8.x4.shared.b16 {%0,%1,%2,%3}, [%4];" \
        : "=r"((r)[0]), "=r"((r)[1]), "=r"((r)[2]), "=r"((r)[3]) : "r"(a))

__device__ __forceinline__ float4 ldcg4(const float* p) {
    float4 v;
    asm volatile("ld.global.cg.v4.f32 {%0,%1,%2,%3}, [%4];"
                 : "=f"(v.x), "=f"(v.y), "=f"(v.z), "=f"(v.w) : "l"(p));
    return v;
}
__device__ __forceinline__ void bar_sync(int id) {
    asm volatile("bar.sync %0, %1;" :: "r"(id), "n"(BAR_CNT) : "memory");
}
__device__ __forceinline__ void bar_arrive(int id) {
    asm volatile("bar.arrive %0, %1;" :: "r"(id), "n"(BAR_CNT) : "memory");
}

// ---------------- grid barrier ---------------------------------------------
__device__ __forceinline__ void gridbar() {
    __syncthreads();
    if (threadIdx.x == 0) {
        unsigned gen = g_bar_gen;
        __threadfence();
        if (atomicAdd(&g_bar_cnt, 1u) == NBLK - 1u) {
            g_bar_cnt = 0u;
            __threadfence();
            g_bar_gen = gen + 1u;
        } else {
            while (g_bar_gen == gen) { __nanosleep(32); }
        }
        __threadfence();
    }
    __syncthreads();
}

// ---------------- init: bf16 conversions + state zero -----------------------
__device__ __forceinline__ uint32_t packbf(float a, float b) {
    __nv_bfloat162 v = __floats2bfloat162_rn(a, b);
    return *(uint32_t*)&v;
}
__device__ void cvt_arr(const float* __restrict__ src, __nv_bfloat16* dst,
                        int n, int g, int GT)
{
    const float4* s4 = (const float4*)src;
    uint2* d4 = (uint2*)dst;
    for (int i = g; i < n / 4; i += GT) {
        float4 v = s4[i];
        d4[i] = make_uint2(packbf(v.x, v.y), packbf(v.z, v.w));
    }
}
__device__ void init_phase(const float* __restrict__ x,
                           const float* __restrict__ Wih0,
                           const float* __restrict__ Whh0,
                           const float* __restrict__ Wih1,
                           const float* __restrict__ Whh1)
{
    const int g = blockIdx.x * NTHR + threadIdx.x;
    const int GT = NBLK * NTHR;
    uint32_t* hA = (uint32_t*)g_hA;
    uint32_t* hB = (uint32_t*)g_hB;
    for (int i = g; i < BD * 1024 / 2; i += GT) { hA[i] = 0u; hB[i] = 0u; }
    for (int i = g; i < BD * HD; i += GT) { g_c0[i] = 0.f; g_c1[i] = 0.f; }
    for (int i = g; i < BD * ID; i += GT) {
        int b = i >> 7, col = i & 127;
        g_din[i] = __float2bfloat16(
            x[(size_t)b * (TENC * ID) + (size_t)(TENC - 1) * ID + col]);
    }
    cvt_arr(x,    g_xb,    BD * TENC * ID, g, GT);
    cvt_arr(Wih0, g_rWih0, 2048 * 128, g, GT);
    cvt_arr(Whh0, g_rWhh0, 2048 * 512, g, GT);
    cvt_arr(Wih1, g_rWih1, 2048 * 512, g, GT);
    cvt_arr(Whh1, g_rWhh1, 2048 * 512, g, GT);
}

// ---------------- fused GEMM + gates phase (warp-specialized, bf16) ---------
// CTA tile: 128 batch rows x 128 gate cols ({i,f,g,o} x 32 j at j0).
// Warps 0-7: consumers (2x4 grid, 64m x 32n). Warps 8-11: producers.
__device__ void phase_layer(char* smem, float* sbias,
                            const __nv_bfloat16* A1, size_t lda1, int KA1,
                            const __nv_bfloat16* A2, int lda2,
                            const __nv_bfloat16* W1, int ldw1, int KW1,
                            const __nv_bfloat16* W2, int ldw2,
                            const float* bih, const float* bhh,
                            float* cbuf, __nv_bfloat16* hdst, float* hfp,
                            int KT)
{
    const int tid  = threadIdx.x;
    const int warp = tid >> 5, lane = tid & 31;
    const int m0 = (blockIdx.x >> 4) * 128;
    const int j0 = (blockIdx.x & 15) * 32;
    const int nch = KT >> 6;             // #k64 chunks (10 or 16)

    if (tid < 128) {
        int n = (tid >> 5) * 512 + j0 + (tid & 31);
        sbias[tid] = bih[n] + bhh[n];
    }

    const uint32_t sA = smem_u32(smem);
    const uint32_t sB = sA + (uint32_t)TILEB;

    if (warp >= 8) {
        // ================= producer path =================
        const int p = tid - 256;                   // 0..127
        const uint32_t dA = sA + (uint32_t)p * ROWB;
        const uint32_t dB = sB + (uint32_t)p * ROWB;
        const int nrow = (p >> 5) * 512 + j0 + (p & 31);
        const __nv_bfloat16* a1r = A1 + (size_t)(m0 + p) * lda1;
        const __nv_bfloat16* a2r = A2 + (size_t)(m0 + p) * lda2 - KA1;
        const __nv_bfloat16* w1r = W1 + (size_t)nrow * ldw1;
        const __nv_bfloat16* w2r = W2 + (size_t)nrow * ldw2 - KW1;

        for (int ch = 0; ch < nch; ch++) {
            int st = ch - (ch / NST) * NST;
            int k0 = ch * 64;
            bar_sync(4 + st);                      // stage free?
            const __nv_bfloat16* srcA = (k0 < KA1) ? a1r + k0 : a2r + k0;
            const __nv_bfloat16* srcB = (k0 < KW1) ? w1r + k0 : w2r + k0;
            uint32_t da = dA + (uint32_t)st * STB;
            uint32_t db = dB + (uint32_t)st * STB;
#pragma unroll
            for (int q = 0; q < 8; q++) {          // 8 x 16B = 128B per row
                cp16(da + q * 16u, srcA + q * 8);
                cp16(db + q * 16u, srcB + q * 8);
            }
            asm volatile("cp.async.commit_group;" ::: "memory");
            if (ch > 0) {
                asm volatile("cp.async.wait_group 1;" ::: "memory");
                int pst = (ch - 1) - ((ch - 1) / NST) * NST;
                bar_arrive(1 + pst);               // stage ch-1 full
            }
        }
        asm volatile("cp.async.wait_group 0;" ::: "memory");
        {
            int pst = (nch - 1) - ((nch - 1) / NST) * NST;
            bar_arrive(1 + pst);
        }
    } else {
        // ================= consumer path =================
        const int wm = (warp >> 2) * 64;
        const int wn = (warp & 3) * 32;
        const uint32_t offA = sA + (uint32_t)((lane & 15) * ROWB)
                                 + (uint32_t)((lane >> 4) * 16)
                                 + (uint32_t)wm * ROWB;
        const uint32_t offB = sB + (uint32_t)((lane & 15) * ROWB)
                                 + (uint32_t)((lane >> 4) * 16)
                                 + (uint32_t)wn * ROWB;

        float acc[4][4][4];
#pragma unroll
        for (int mi = 0; mi < 4; mi++)
#pragma unroll
            for (int ni = 0; ni < 4; ni++)
#pragma unroll
                for (int r = 0; r < 4; r++) acc[mi][ni][r] = 0.f;

        for (int ch = 0; ch < nch; ch++) {
            int st = ch - (ch / NST) * NST;
            bar_sync(1 + st);                      // wait stage full
            const uint32_t so = (uint32_t)st * STB;
#pragma unroll
            for (int ks = 0; ks < 4; ks++) {       // four k16 steps of k64
                const uint32_t ko = (uint32_t)(ks * 32);   // 16 els * 2B
                uint32_t fb0[4], fb1[4];
                LDSM4(fb0, offB + so + ko);                      // n 0-15
                LDSM4(fb1, offB + so + 16u * ROWB + ko);         // n 16-31
#pragma unroll
                for (int mi = 0; mi < 4; mi++) {
                    uint32_t fa[4];
                    LDSM4(fa, offA + so + (uint32_t)(mi * 16 * ROWB) + ko);
                    mma16(acc[mi][0], fa[0], fa[1], fa[2], fa[3], fb0[0], fb0[2]);
                    mma16(acc[mi][1], fa[0], fa[1], fa[2], fa[3], fb0[1], fb0[3]);
                    mma16(acc[mi][2], fa[0], fa[1], fa[2], fa[3], fb1[0], fb1[2]);
                    mma16(acc[mi][3], fa[0], fa[1], fa[2], fa[3], fb1[1], fb1[3]);
                }
            }
            bar_arrive(4 + st);                    // stage consumed
        }

        __syncthreads();                           // pair with producers below
        {
            const int gid = lane >> 2, t4 = lane & 3;
            float* zb = (float*)smem;
#pragma unroll
            for (int mi = 0; mi < 4; mi++) {
                int r0 = wm + mi * 16 + gid;
#pragma unroll
                for (int ni = 0; ni < 4; ni++) {
                    int c = wn + ni * 8 + t4 * 2;
                    *(float2*)&zb[(size_t)r0 * 132 + c]       = make_float2(acc[mi][ni][0], acc[mi][ni][1]);
                    *(float2*)&zb[(size_t)(r0 + 8) * 132 + c] = make_float2(acc[mi][ni][2], acc[mi][ni][3]);
                }
            }
        }
    }

    if (warp >= 8) __syncthreads();                // producers' pairing sync
    __syncthreads();                               // zb visible to all

    // ---- gate epilogue over ALL 384 threads (warp-per-row, coalesced) ----
    {
        float* zb = (float*)smem;
        for (int idx = tid; idx < 4096; idx += NTHR) {
            const int row = idx >> 5;              // 0..127
            const int j   = idx & 31;
            const int m   = m0 + row;
            const float* zr = zb + (size_t)row * 132;
            float zi = zr[j]      + sbias[j];
            float zf = zr[32 + j] + sbias[32 + j];
            float zg = zr[64 + j] + sbias[64 + j];
            float zo = zr[96 + j] + sbias[96 + j];
            float* cp_ = cbuf + (size_t)m * HD + j0 + j;
            float c = sig_a(zf) * (*cp_) + sig_a(zi) * tanh_a(zg);
            *cp_ = c;
            float h = sig_a(zo) * tanh_a(c);
            hdst[(size_t)m * 1024 + j0 + j] = __float2bfloat16(h);
            if (hfp) hfp[(size_t)m * HD + j0 + j] = h;
        }
    }
    __syncthreads();
}

// ---------------- fc phase (decoder projection, fp32) ------------------------
__device__ void fc_phase(char* smem,
                         const float* __restrict__ fcw,
                         const float* __restrict__ fcb,
                         float* __restrict__ out, int t)
{
    const int m0 = (blockIdx.x >> 2) * 32;     // 32 batch rows
    const int c0 = (blockIdx.x & 3) * 32;      // 32 out cols
    const int tid = threadIdx.x;
    float* hs = (float*)smem;                  // 32 x 136 floats

    float a0 = 0.f, a1 = 0.f, a2 = 0.f, a3 = 0.f;
    const int r  = (tid & 255) >> 3;
    const int cq = c0 + (tid & 7) * 4;

    for (int kc = 0; kc < HD; kc += 128) {
        __syncthreads();
        if (tid < 256) {   // load fp32 h1 tile 32 x 128 (cross-CTA: bypass L1)
            int rr = tid >> 3, u = (tid & 7) * 16;
            const float* src = g_h1f + (size_t)(m0 + rr) * HD + kc + u;
            float* dst = hs + (size_t)rr * 136 + u;
#pragma unroll
            for (int q = 0; q < 4; q++)
                *(float4*)(dst + q * 4) = ldcg4(src + q * 4);
        }
        __syncthreads();
        if (tid < 256) {
            const float* hr = hs + (size_t)r * 136;
            const float4* w0 = (const float4*)(fcw + (size_t)(cq + 0) * HD + kc);
            const float4* w1 = (const float4*)(fcw + (size_t)(cq + 1) * HD + kc);
            const float4* w2 = (const float4*)(fcw + (size_t)(cq + 2) * HD + kc);
            const float4* w3 = (const float4*)(fcw + (size_t)(cq + 3) * HD + kc);
#pragma unroll 8
            for (int k4 = 0; k4 < 32; k4++) {
                float4 h4 = *(const float4*)(hr + k4 * 4);
                float4 v0 = __ldg(w0 + k4), v1 = __ldg(w1 + k4);
                float4 v2 = __ldg(w2 + k4), v3 = __ldg(w3 + k4);
                a0 += h4.x * v0.x + h4.y * v0.y + h4.z * v0.z + h4.w * v0.w;
                a1 += h4.x * v1.x + h4.y * v1.y + h4.z * v1.z + h4.w * v1.w;
                a2 += h4.x * v2.x + h4.y * v2.y + h4.z * v2.z + h4.w * v2.w;
                a3 += h4.x * v3.x + h4.y * v3.y + h4.z * v3.z + h4.w * v3.w;
            }
        }
    }
    if (tid < 256) {
        float4 res = make_float4(a0 + fcb[cq], a1 + fcb[cq + 1],
                                 a2 + fcb[cq + 2], a3 + fcb[cq + 3]);
        *(float4*)(out + (size_t)(m0 + r) * (TDEC * ID) + (size_t)t * ID + cq) = res;
        __nv_bfloat16* dp = g_din + (size_t)(m0 + r) * ID + cq;
        uint2 dv = make_uint2(packbf(res.x, res.y), packbf(res.z, res.w));
        *(uint2*)dp = dv;
    }
    __syncthreads();
}

// ---------------- persistent kernel -----------------------------------------
__global__ void __launch_bounds__(NTHR, 1)
lstm_persistent(const float* __restrict__ x,
                const float* __restrict__ Wih0, const float* __restrict__ Whh0,
                const float* __restrict__ bih0, const float* __restrict__ bhh0,
                const float* __restrict__ Wih1, const float* __restrict__ Whh1,
                const float* __restrict__ bih1, const float* __restrict__ bhh1,
                const float* __restrict__ fcw,  const float* __restrict__ fcb,
                float* __restrict__ out)
{
    extern __shared__ char dyn[];        // NST * STB = 110592 B
    __shared__ float s_bias[128];

    // prime EMPTY barriers: one consumer-side arrival round per stage
    if (threadIdx.x < 256) {
        bar_arrive(4); bar_arrive(5); bar_arrive(6);
    }

    init_phase(x, Wih0, Whh0, Wih1, Whh1);
    gridbar();

    for (int t = 0; t < TENC; t++) {
        __nv_bfloat16* cur  = (t & 1) ? g_hB : g_hA;
        __nv_bfloat16* prev = (t & 1) ? g_hA : g_hB;
        phase_layer(dyn, s_bias,
                    g_xb + (size_t)t * ID, (size_t)TENC * ID, 128, prev, 1024,
                    g_rWih0, 128, 128, g_rWhh0, 512,
                    bih0, bhh0, g_c0, cur, nullptr, 640);
        gridbar();
        phase_layer(dyn, s_bias,
                    cur, 1024, 512, prev + 512, 1024,
                    g_rWih1, 512, 512, g_rWhh1, 512,
                    bih1, bhh1, g_c1, cur + 512, nullptr, 1024);
        gridbar();
    }

    for (int t = 0; t < TDEC; t++) {
        __nv_bfloat16* cur  = (t & 1) ? g_hB : g_hA;
        __nv_bfloat16* prev = (t & 1) ? g_hA : g_hB;
        phase_layer(dyn, s_bias,
                    g_din, ID, 128, prev, 1024,
                    g_rWih0, 128, 128, g_rWhh0, 512,
                    bih0, bhh0, g_c0, cur, nullptr, 640);
        gridbar();
        phase_layer(dyn, s_bias,
                    cur, 1024, 512, prev + 512, 1024,
                    g_rWih1, 512, 512, g_rWhh1, 512,
                    bih1, bhh1, g_c1, cur + 512, g_h1f, 1024);
        gridbar();
        fc_phase(dyn, fcw, fcb, out, t);
        gridbar();
    }
}

// ---------------- entry ------------------------------------------------------
extern "C" void kernel_launch(void* const* d_in, const int* in_sizes, int n_in,
                              void* d_out, int out_size)
{
    const int smem = NST * STB;          // 110592
    cudaFuncSetAttribute(lstm_persistent,
                         cudaFuncAttributeMaxDynamicSharedMemorySize, smem);
    lstm_persistent<<<NBLK, NTHR, smem>>>(
        (const float*)d_in[0],
        (const float*)d_in[1], (const float*)d_in[2],
        (const float*)d_in[3], (const float*)d_in[4],
        (const float*)d_in[5], (const float*)d_in[6],
        (const float*)d_in[7], (const float*)d_in[8],
        (const float*)d_in[9], (const float*)d_in[10],
        (float*)d_out);
}

// round 14
// speedup vs baseline: 2.3277x; 1.2413x over previous
#include <cuda_runtime.h>
#include <cuda_bf16.h>
#include <math.h>
#include <cstdint>

#define BD   1024
#define HD   512
#define TENC 384
#define TDEC 128
#define ID   128
#define NBLK 128
#define NTHR 384           // 8 consumer warps + 4 producer warps

#define ROWB 144           // smem row stride bytes (64 bf16 = 128B + 16B pad)
#define TILEB (128 * ROWB) // 18432 per operand tile
#define STB  (2 * TILEB)   // 36864 per stage (A + B)
#define NST  3

#define BAR_CNT 384        // named barriers: FULL[st]=1+st, EMPTY[st]=4+st
#define NGRP   8           // m-groups of 16 CTAs each

// ---------------- static device scratch ------------------------------------
__device__ __align__(16) __nv_bfloat16 g_hA[BD * 1024];   // ping-pong [h0|h1]
__device__ __align__(16) __nv_bfloat16 g_hB[BD * 1024];
__device__ __align__(16) float         g_h1f[BD * HD];    // fp32 h1 for fc
__device__ __align__(16) float g_c0 [BD * HD];
__device__ __align__(16) float g_c1 [BD * HD];
__device__ __align__(16) __nv_bfloat16 g_din[BD * ID];
__device__ __align__(16) __nv_bfloat16 g_xb [BD * TENC * ID];   // bf16 x copy
__device__ __align__(16) __nv_bfloat16 g_rWih0[2048 * 128];
__device__ __align__(16) __nv_bfloat16 g_rWhh0[2048 * 512];
__device__ __align__(16) __nv_bfloat16 g_rWih1[2048 * 512];
__device__ __align__(16) __nv_bfloat16 g_rWhh1[2048 * 512];
__device__ unsigned          g_bar_cnt;
__device__ volatile unsigned g_bar_gen;
// per-group barriers (256B spacing => no L2-line sharing between groups)
__device__ unsigned          g_gcnt[NGRP * 64];
__device__ volatile unsigned g_ggen[NGRP * 64];

// ---------------- helpers --------------------------------------------------
__device__ __forceinline__ uint32_t smem_u32(const void* p) {
    uint32_t a;
    asm("{ .reg .u64 t; cvta.to.shared.u64 t, %1; cvt.u32.u64 %0, t; }"
        : "=r"(a) : "l"(p));
    return a;
}
__device__ __forceinline__ float tanh_a(float x) {
    float r;
    asm("tanh.approx.f32 %0, %1;" : "=f"(r) : "f"(x));
    return r;
}
__device__ __forceinline__ float sig_a(float x) {
    return fmaf(0.5f, tanh_a(0.5f * x), 0.5f);
}
__device__ __forceinline__ void cp16(uint32_t dst, const void* src) {
    asm volatile("cp.async.cg.shared.global [%0], [%1], 16;"
                 :: "r"(dst), "l"(src) : "memory");
}
__device__ __forceinline__ void mma16(float* c, uint32_t a0, uint32_t a1,
                                      uint32_t a2, uint32_t a3,
                                      uint32_t b0, uint32_t b1) {
    asm volatile("mma.sync.aligned.m16n8k16.row.col.f32.bf16.bf16.f32 "
                 "{%0,%1,%2,%3}, {%4,%5,%6,%7}, {%8,%9}, {%0,%1,%2,%3};"
                 : "+f"(c[0]), "+f"(c[1]), "+f"(c[2]), "+f"(c[3])
                 : "r"(a0), "r"(a1), "r"(a2), "r"(a3), "r"(b0), "r"(b1));
}
#define LDSM4(r, a)                                                          \
    asm volatile("ldmatrix.sync.aligned.m8n8.x4.shared.b16 {%0,%1,%2,%3}, [%4];" \
        : "=r"((r)[0]), "=r"((r)[1]), "=r"((r)[2]), "=r"((r)[3]) : "r"(a))

__device__ __forceinline__ float4 ldcg4(const float* p) {
    float4 v;
    asm volatile("ld.global.cg.v4.f32 {%0,%1,%2,%3}, [%4];"
                 : "=f"(v.x), "=f"(v.y), "=f"(v.z), "=f"(v.w) : "l"(p));
    return v;
}
__device__ __forceinline__ void bar_sync(int id) {
    asm volatile("bar.sync %0, %1;" :: "r"(id), "n"(BAR_CNT) : "memory");
}
__device__ __forceinline__ void bar_arrive(int id) {
    asm volatile("bar.arrive %0, %1;" :: "r"(id), "n"(BAR_CNT) : "memory");
}

// ---------------- barriers ---------------------------------------------------
__device__ __forceinline__ void gridbar() {       // global (init only)
    __syncthreads();
    if (threadIdx.x == 0) {
        unsigned gen = g_bar_gen;
        __threadfence();
        if (atomicAdd(&g_bar_cnt, 1u) == NBLK - 1u) {
            g_bar_cnt = 0u;
            __threadfence();
            g_bar_gen = gen + 1u;
        } else {
            while (g_bar_gen == gen) { __nanosleep(32); }
        }
        __threadfence();
    }
    __syncthreads();
}
__device__ __forceinline__ void groupbar() {      // 16-CTA m-group barrier
    const int gq = (blockIdx.x >> 4) * 64;
    __syncthreads();
    if (threadIdx.x == 0) {
        unsigned gen = g_ggen[gq];
        __threadfence();
        if (atomicAdd(&g_gcnt[gq], 1u) == 15u) {
            g_gcnt[gq] = 0u;
            __threadfence();
            g_ggen[gq] = gen + 1u;
        } else {
            while (g_ggen[gq] == gen) { __nanosleep(32); }
        }
        __threadfence();
    }
    __syncthreads();
}

// ---------------- init: bf16 conversions + state zero -----------------------
__device__ __forceinline__ uint32_t packbf(float a, float b) {
    __nv_bfloat162 v = __floats2bfloat162_rn(a, b);
    return *(uint32_t*)&v;
}
__device__ void cvt_arr(const float* __restrict__ src, __nv_bfloat16* dst,
                        int n, int g, int GT)
{
    const float4* s4 = (const float4*)src;
    uint2* d4 = (uint2*)dst;
    for (int i = g; i < n / 4; i += GT) {
        float4 v = s4[i];
        d4[i] = make_uint2(packbf(v.x, v.y), packbf(v.z, v.w));
    }
}
__device__ void init_phase(const float* __restrict__ x,
                           const float* __restrict__ Wih0,
                           const float* __restrict__ Whh0,
                           const float* __restrict__ Wih1,
                           const float* __restrict__ Whh1)
{
    const int g = blockIdx.x * NTHR + threadIdx.x;
    const int GT = NBLK * NTHR;
    uint32_t* hA = (uint32_t*)g_hA;
    uint32_t* hB = (uint32_t*)g_hB;
    for (int i = g; i < BD * 1024 / 2; i += GT) { hA[i] = 0u; hB[i] = 0u; }
    for (int i = g; i < BD * HD; i += GT) { g_c0[i] = 0.f; g_c1[i] = 0.f; }
    for (int i = g; i < BD * ID; i += GT) {
        int b = i >> 7, col = i & 127;
        g_din[i] = __float2bfloat16(
            x[(size_t)b * (TENC * ID) + (size_t)(TENC - 1) * ID + col]);
    }
    cvt_arr(x,    g_xb,    BD * TENC * ID, g, GT);
    cvt_arr(Wih0, g_rWih0, 2048 * 128, g, GT);
    cvt_arr(Whh0, g_rWhh0, 2048 * 512, g, GT);
    cvt_arr(Wih1, g_rWih1, 2048 * 512, g, GT);
    cvt_arr(Whh1, g_rWhh1, 2048 * 512, g, GT);
}

// ---------------- fused GEMM + gates phase (warp-specialized, bf16) ---------
// CTA tile: 128 batch rows x 128 gate cols ({i,f,g,o} x 32 j at j0).
__device__ void phase_layer(char* smem, float* sbias,
                            const __nv_bfloat16* A1, size_t lda1, int KA1,
                            const __nv_bfloat16* A2, int lda2,
                            const __nv_bfloat16* W1, int ldw1, int KW1,
                            const __nv_bfloat16* W2, int ldw2,
                            const float* bih, const float* bhh,
                            float* cbuf, __nv_bfloat16* hdst, float* hfp,
                            int KT)
{
    const int tid  = threadIdx.x;
    const int warp = tid >> 5, lane = tid & 31;
    const int m0 = (blockIdx.x >> 4) * 128;
    const int j0 = (blockIdx.x & 15) * 32;
    const int nch = KT >> 6;             // #k64 chunks (10 or 16)

    if (tid < 128) {
        int n = (tid >> 5) * 512 + j0 + (tid & 31);
        sbias[tid] = bih[n] + bhh[n];
    }

    const uint32_t sA = smem_u32(smem);
    const uint32_t sB = sA + (uint32_t)TILEB;

    if (warp >= 8) {
        // ================= producer path =================
        const int p = tid - 256;                   // 0..127
        const uint32_t dA = sA + (uint32_t)p * ROWB;
        const uint32_t dB = sB + (uint32_t)p * ROWB;
        const int nrow = (p >> 5) * 512 + j0 + (p & 31);
        const __nv_bfloat16* a1r = A1 + (size_t)(m0 + p) * lda1;
        const __nv_bfloat16* a2r = A2 + (size_t)(m0 + p) * lda2 - KA1;
        const __nv_bfloat16* w1r = W1 + (size_t)nrow * ldw1;
        const __nv_bfloat16* w2r = W2 + (size_t)nrow * ldw2 - KW1;

        for (int ch = 0; ch < nch; ch++) {
            int st = ch - (ch / NST) * NST;
            int k0 = ch * 64;
            bar_sync(4 + st);                      // stage free?
            const __nv_bfloat16* srcA = (k0 < KA1) ? a1r + k0 : a2r + k0;
            const __nv_bfloat16* srcB = (k0 < KW1) ? w1r + k0 : w2r + k0;
            uint32_t da = dA + (uint32_t)st * STB;
            uint32_t db = dB + (uint32_t)st * STB;
#pragma unroll
            for (int q = 0; q < 8; q++) {          // 8 x 16B = 128B per row
                cp16(da + q * 16u, srcA + q * 8);
                cp16(db + q * 16u, srcB + q * 8);
            }
            asm volatile("cp.async.commit_group;" ::: "memory");
            if (ch > 0) {
                asm volatile("cp.async.wait_group 1;" ::: "memory");
                int pst = (ch - 1) - ((ch - 1) / NST) * NST;
                bar_arrive(1 + pst);               // stage ch-1 full
            }
        }
        asm volatile("cp.async.wait_group 0;" ::: "memory");
        {
            int pst = (nch - 1) - ((nch - 1) / NST) * NST;
            bar_arrive(1 + pst);
        }
    } else {
        // ================= consumer path =================
        const int wm = (warp >> 2) * 64;
        const int wn = (warp & 3) * 32;
        const uint32_t offA = sA + (uint32_t)((lane & 15) * ROWB)
                                 + (uint32_t)((lane >> 4) * 16)
                                 + (uint32_t)wm * ROWB;
        const uint32_t offB = sB + (uint32_t)((lane & 15) * ROWB)
                                 + (uint32_t)((lane >> 4) * 16)
                                 + (uint32_t)wn * ROWB;

        float acc[4][4][4];
#pragma unroll
        for (int mi = 0; mi < 4; mi++)
#pragma unroll
            for (int ni = 0; ni < 4; ni++)
#pragma unroll
                for (int r = 0; r < 4; r++) acc[mi][ni][r] = 0.f;

        for (int ch = 0; ch < nch; ch++) {
            int st = ch - (ch / NST) * NST;
            bar_sync(1 + st);                      // wait stage full
            const uint32_t so = (uint32_t)st * STB;
#pragma unroll
            for (int ks = 0; ks < 4; ks++) {       // four k16 steps of k64
                const uint32_t ko = (uint32_t)(ks * 32);   // 16 els * 2B
                uint32_t fb0[4], fb1[4];
                LDSM4(fb0, offB + so + ko);                      // n 0-15
                LDSM4(fb1, offB + so + 16u * ROWB + ko);         // n 16-31
#pragma unroll
                for (int mi = 0; mi < 4; mi++) {
                    uint32_t fa[4];
                    LDSM4(fa, offA + so + (uint32_t)(mi * 16 * ROWB) + ko);
                    mma16(acc[mi][0], fa[0], fa[1], fa[2], fa[3], fb0[0], fb0[2]);
                    mma16(acc[mi][1], fa[0], fa[1], fa[2], fa[3], fb0[1], fb0[3]);
                    mma16(acc[mi][2], fa[0], fa[1], fa[2], fa[3], fb1[0], fb1[2]);
                    mma16(acc[mi][3], fa[0], fa[1], fa[2], fa[3], fb1[1], fb1[3]);
                }
            }
            bar_arrive(4 + st);                    // stage consumed
        }

        __syncthreads();                           // pair with producers below
        {
            const int gid = lane >> 2, t4 = lane & 3;
            float* zb = (float*)smem;
#pragma unroll
            for (int mi = 0; mi < 4; mi++) {
                int r0 = wm + mi * 16 + gid;
#pragma unroll
                for (int ni = 0; ni < 4; ni++) {
                    int c = wn + ni * 8 + t4 * 2;
                    *(float2*)&zb[(size_t)r0 * 132 + c]       = make_float2(acc[mi][ni][0], acc[mi][ni][1]);
                    *(float2*)&zb[(size_t)(r0 + 8) * 132 + c] = make_float2(acc[mi][ni][2], acc[mi][ni][3]);
                }
            }
        }
    }

    if (warp >= 8) __syncthreads();                // producers' pairing sync
    __syncthreads();                               // zb visible to all

    // ---- gate epilogue over ALL 384 threads (warp-per-row, coalesced) ----
    {
        float* zb = (float*)smem;
        for (int idx = tid; idx < 4096; idx += NTHR) {
            const int row = idx >> 5;              // 0..127
            const int j   = idx & 31;
            const int m   = m0 + row;
            const float* zr = zb + (size_t)row * 132;
            float zi = zr[j]      + sbias[j];
            float zf = zr[32 + j] + sbias[32 + j];
            float zg = zr[64 + j] + sbias[64 + j];
            float zo = zr[96 + j] + sbias[96 + j];
            float* cp_ = cbuf + (size_t)m * HD + j0 + j;
            float c = sig_a(zf) * (*cp_) + sig_a(zi) * tanh_a(zg);
            *cp_ = c;
            float h = sig_a(zo) * tanh_a(c);
            hdst[(size_t)m * 1024 + j0 + j] = __float2bfloat16(h);
            if (hfp) hfp[(size_t)m * HD + j0 + j] = h;
        }
    }
    __syncthreads();
}

// ---------------- fc phase: group-local (16 CTAs of one m-group) -------------
// CTA (group gq, j-index jx) projects its own 8 batch rows.
__device__ void fc_group(char* smem,
                         const float* __restrict__ fcw,
                         const float* __restrict__ fcb,
                         float* __restrict__ out, int t)
{
    const int gq = blockIdx.x >> 4, jx = blockIdx.x & 15;
    const int r0 = gq * 128 + jx * 8;          // this CTA's 8 batch rows
    const int tid = threadIdx.x;
    float* hs = (float*)smem;                  // 8 x 512 fp32 = 16 KB

    // stage h1f rows (cross-CTA within group: bypass L1)
    for (int i = tid * 4; i < 8 * HD; i += NTHR * 4) {
        int rr = i >> 9, u = i & 511;
        *(float4*)(hs + rr * HD + u) = ldcg4(g_h1f + (size_t)(r0 + rr) * HD + u);
    }
    __syncthreads();

    if (tid < 256) {
        const int col   = tid & 127;
        const int rbase = tid >> 7;            // 0 or 1; rows rbase+2i
        float a0 = 0.f, a1 = 0.f, a2 = 0.f, a3 = 0.f;
        const float4* w = (const float4*)(fcw + (size_t)col * HD);
        const float* h0p = hs + (rbase + 0) * HD;
        const float* h1p = hs + (rbase + 2) * HD;
        const float* h2p = hs + (rbase + 4) * HD;
        const float* h3p = hs + (rbase + 6) * HD;
#pragma unroll 4
        for (int k4 = 0; k4 < HD / 4; k4++) {
            float4 wv = __ldg(w + k4);
            float4 x0 = *(const float4*)(h0p + k4 * 4);
            float4 x1 = *(const float4*)(h1p + k4 * 4);
            float4 x2 = *(const float4*)(h2p + k4 * 4);
            float4 x3 = *(const float4*)(h3p + k4 * 4);
            a0 += x0.x * wv.x + x0.y * wv.y + x0.z * wv.z + x0.w * wv.w;
            a1 += x1.x * wv.x + x1.y * wv.y + x1.z * wv.z + x1.w * wv.w;
            a2 += x2.x * wv.x + x2.y * wv.y + x2.z * wv.z + x2.w * wv.w;
            a3 += x3.x * wv.x + x3.y * wv.y + x3.z * wv.z + x3.w * wv.w;
        }
        float b = fcb[col];
        float r[4] = {a0 + b, a1 + b, a2 + b, a3 + b};
#pragma unroll
        for (int i = 0; i < 4; i++) {
            int m = r0 + rbase + 2 * i;
            out[(size_t)m * (TDEC * ID) + (size_t)t * ID + col] = r[i];
            g_din[(size_t)m * ID + col] = __float2bfloat16(r[i]);
        }
    }
    __syncthreads();
}

// ---------------- persistent kernel -----------------------------------------
__global__ void __launch_bounds__(NTHR, 1)
lstm_persistent(const float* __restrict__ x,
                const float* __restrict__ Wih0, const float* __restrict__ Whh0,
                const float* __restrict__ bih0, const float* __restrict__ bhh0,
                const float* __restrict__ Wih1, const float* __restrict__ Whh1,
                const float* __restrict__ bih1, const float* __restrict__ bhh1,
                const float* __restrict__ fcw,  const float* __restrict__ fcb,
                float* __restrict__ out)
{
    extern __shared__ char dyn[];        // NST * STB = 110592 B
    __shared__ float s_bias[128];

    // prime EMPTY barriers: one consumer-side arrival round per stage
    if (threadIdx.x < 256) {
        bar_arrive(4); bar_arrive(5); bar_arrive(6);
    }

    init_phase(x, Wih0, Whh0, Wih1, Whh1);
    gridbar();                           // ONLY global barrier

    // ======== encoder: wavefront {layer0[p], layer1[p-1]} per phase ========
    for (int p = 0; p <= TENC; p++) {
        if (p < TENC) {
            int t = p;
            __nv_bfloat16* cur  = (t & 1) ? g_hB : g_hA;
            __nv_bfloat16* prev = (t & 1) ? g_hA : g_hB;
            phase_layer(dyn, s_bias,
                        g_xb + (size_t)t * ID, (size_t)TENC * ID, 128, prev, 1024,
                        g_rWih0, 128, 128, g_rWhh0, 512,
                        bih0, bhh0, g_c0, cur, nullptr, 640);
        }
        if (p >= 1) {
            int t1 = p - 1;
            __nv_bfloat16* cur  = (t1 & 1) ? g_hB : g_hA;
            __nv_bfloat16* prev = (t1 & 1) ? g_hA : g_hB;
            phase_layer(dyn, s_bias,
                        cur, 1024, 512, prev + 512, 1024,
                        g_rWih1, 512, 512, g_rWhh1, 512,
                        bih1, bhh1, g_c1, cur + 512, nullptr, 1024);
        }
        groupbar();
    }

    // ======== decoder: serial per step, group-local barriers ========
    for (int t = 0; t < TDEC; t++) {
        __nv_bfloat16* cur  = (t & 1) ? g_hB : g_hA;   // TENC even: parity ok
        __nv_bfloat16* prev = (t & 1) ? g_hA : g_hB;
        phase_layer(dyn, s_bias,
                    g_din, ID, 128, prev, 1024,
                    g_rWih0, 128, 128, g_rWhh0, 512,
                    bih0, bhh0, g_c0, cur, nullptr, 640);
        groupbar();
        phase_layer(dyn, s_bias,
                    cur, 1024, 512, prev + 512, 1024,
                    g_rWih1, 512, 512, g_rWhh1, 512,
                    bih1, bhh1, g_c1, cur + 512, g_h1f, 1024);
        groupbar();
        fc_group(dyn, fcw, fcb, out, t);
        groupbar();
    }
}

// ---------------- entry ------------------------------------------------------
extern "C" void kernel_launch(void* const* d_in, const int* in_sizes, int n_in,
                              void* d_out, int out_size)
{
    const int smem = NST * STB;          // 110592
    cudaFuncSetAttribute(lstm_persistent,
                         cudaFuncAttributeMaxDynamicSharedMemorySize, smem);
    lstm_persistent<<<NBLK, NTHR, smem>>>(
        (const float*)d_in[0],
        (const float*)d_in[1], (const float*)d_in[2],
        (const float*)d_in[3], (const float*)d_in[4],
        (const float*)d_in[5], (const float*)d_in[6],
        (const float*)d_in[7], (const float*)d_in[8],
        (const float*)d_in[9], (const float*)d_in[10],
        (float*)d_out);
}

// round 15
// speedup vs baseline: 2.3465x; 1.0080x over previous
#include <cuda_runtime.h>
#include <cuda_bf16.h>
#include <math.h>
#include <cstdint>

#define BD   1024
#define HD   512
#define TENC 384
#define TDEC 128
#define ID   128
#define NBLK 128
#define NTHR 384           // 8 consumer warps + 4 producer warps

#define ROWB 144           // smem row stride bytes (64 bf16 = 128B + 16B pad)
#define TILEB (128 * ROWB) // 18432 per operand tile
#define STB  (2 * TILEB)   // 36864 per stage (A + B)
#define NST  4             // ring depth (power of two)

#define BAR_CNT 384        // named barriers: FULL[st]=1+st, EMPTY[st]=5+st
#define NGRP   8           // m-groups of 16 CTAs each

// ---------------- static device scratch ------------------------------------
__device__ __align__(16) __nv_bfloat16 g_hA[BD * 1024];   // ping-pong [h0|h1]
__device__ __align__(16) __nv_bfloat16 g_hB[BD * 1024];
__device__ __align__(16) float         g_h1f[BD * HD];    // fp32 h1 for fc
__device__ __align__(16) float g_c0 [BD * HD];
__device__ __align__(16) float g_c1 [BD * HD];
__device__ __align__(16) __nv_bfloat16 g_din[BD * ID];
__device__ __align__(16) __nv_bfloat16 g_xb [BD * TENC * ID];   // bf16 x copy
__device__ __align__(16) __nv_bfloat16 g_rWih0[2048 * 128];
__device__ __align__(16) __nv_bfloat16 g_rWhh0[2048 * 512];
__device__ __align__(16) __nv_bfloat16 g_rWih1[2048 * 512];
__device__ __align__(16) __nv_bfloat16 g_rWhh1[2048 * 512];
__device__ unsigned          g_bar_cnt;
__device__ volatile unsigned g_bar_gen;
// per-group barriers (256B spacing => no L2-line sharing between groups)
__device__ unsigned          g_gcnt[NGRP * 64];
__device__ volatile unsigned g_ggen[NGRP * 64];

// ---------------- helpers --------------------------------------------------
__device__ __forceinline__ uint32_t smem_u32(const void* p) {
    uint32_t a;
    asm("{ .reg .u64 t; cvta.to.shared.u64 t, %1; cvt.u32.u64 %0, t; }"
        : "=r"(a) : "l"(p));
    return a;
}
__device__ __forceinline__ float tanh_a(float x) {
    float r;
    asm("tanh.approx.f32 %0, %1;" : "=f"(r) : "f"(x));
    return r;
}
__device__ __forceinline__ float sig_a(float x) {
    return fmaf(0.5f, tanh_a(0.5f * x), 0.5f);
}
__device__ __forceinline__ void cp16(uint32_t dst, const void* src) {
    asm volatile("cp.async.cg.shared.global [%0], [%1], 16;"
                 :: "r"(dst), "l"(src) : "memory");
}
__device__ __forceinline__ void mma16(float* c, uint32_t a0, uint32_t a1,
                                      uint32_t a2, uint32_t a3,
                                      uint32_t b0, uint32_t b1) {
    asm volatile("mma.sync.aligned.m16n8k16.row.col.f32.bf16.bf16.f32 "
                 "{%0,%1,%2,%3}, {%4,%5,%6,%7}, {%8,%9}, {%0,%1,%2,%3};"
                 : "+f"(c[0]), "+f"(c[1]), "+f"(c[2]), "+f"(c[3])
                 : "r"(a0), "r"(a1), "r"(a2), "r"(a3), "r"(b0), "r"(b1));
}
#define LDSM4(r, a)                                                          \
    asm volatile("ldmatrix.sync.aligned.m8n8.x4.shared.b16 {%0,%1,%2,%3}, [%4];" \
        : "=r"((r)[0]), "=r"((r)[1]), "=r"((r)[2]), "=r"((r)[3]) : "r"(a))

__device__ __forceinline__ float4 ldcg4(const float* p) {
    float4 v;
    asm volatile("ld.global.cg.v4.f32 {%0,%1,%2,%3}, [%4];"
                 : "=f"(v.x), "=f"(v.y), "=f"(v.z), "=f"(v.w) : "l"(p));
    return v;
}
__device__ __forceinline__ void bar_sync(int id) {
    asm volatile("bar.sync %0, %1;" :: "r"(id), "n"(BAR_CNT) : "memory");
}
__device__ __forceinline__ void bar_arrive(int id) {
    asm volatile("bar.arrive %0, %1;" :: "r"(id), "n"(BAR_CNT) : "memory");
}

// ---------------- barriers ---------------------------------------------------
__device__ __forceinline__ void gridbar() {       // global (init only)
    __syncthreads();
    if (threadIdx.x == 0) {
        unsigned gen = g_bar_gen;
        __threadfence();
        if (atomicAdd(&g_bar_cnt, 1u) == NBLK - 1u) {
            g_bar_cnt = 0u;
            __threadfence();
            g_bar_gen = gen + 1u;
        } else {
            while (g_bar_gen == gen) { __nanosleep(32); }
        }
        __threadfence();
    }
    __syncthreads();
}
__device__ __forceinline__ void groupbar() {      // 16-CTA m-group barrier
    const int gq = (blockIdx.x >> 4) * 64;
    __syncthreads();
    if (threadIdx.x == 0) {
        unsigned gen = g_ggen[gq];
        __threadfence();
        if (atomicAdd(&g_gcnt[gq], 1u) == 15u) {
            g_gcnt[gq] = 0u;
            __threadfence();
            g_ggen[gq] = gen + 1u;
        } else {
            while (g_ggen[gq] == gen) { __nanosleep(32); }
        }
        __threadfence();
    }
    __syncthreads();
}

// ---------------- init: bf16 conversions + state zero -----------------------
__device__ __forceinline__ uint32_t packbf(float a, float b) {
    __nv_bfloat162 v = __floats2bfloat162_rn(a, b);
    return *(uint32_t*)&v;
}
__device__ void cvt_arr(const float* __restrict__ src, __nv_bfloat16* dst,
                        int n, int g, int GT)
{
    const float4* s4 = (const float4*)src;
    uint2* d4 = (uint2*)dst;
    for (int i = g; i < n / 4; i += GT) {
        float4 v = s4[i];
        d4[i] = make_uint2(packbf(v.x, v.y), packbf(v.z, v.w));
    }
}
__device__ void init_phase(const float* __restrict__ x,
                           const float* __restrict__ Wih0,
                           const float* __restrict__ Whh0,
                           const float* __restrict__ Wih1,
                           const float* __restrict__ Whh1)
{
    const int g = blockIdx.x * NTHR + threadIdx.x;
    const int GT = NBLK * NTHR;
    uint32_t* hA = (uint32_t*)g_hA;
    uint32_t* hB = (uint32_t*)g_hB;
    for (int i = g; i < BD * 1024 / 2; i += GT) { hA[i] = 0u; hB[i] = 0u; }
    for (int i = g; i < BD * HD; i += GT) { g_c0[i] = 0.f; g_c1[i] = 0.f; }
    for (int i = g; i < BD * ID; i += GT) {
        int b = i >> 7, col = i & 127;
        g_din[i] = __float2bfloat16(
            x[(size_t)b * (TENC * ID) + (size_t)(TENC - 1) * ID + col]);
    }
    cvt_arr(x,    g_xb,    BD * TENC * ID, g, GT);
    cvt_arr(Wih0, g_rWih0, 2048 * 128, g, GT);
    cvt_arr(Whh0, g_rWhh0, 2048 * 512, g, GT);
    cvt_arr(Wih1, g_rWih1, 2048 * 512, g, GT);
    cvt_arr(Whh1, g_rWhh1, 2048 * 512, g, GT);
}

// ---------------- fused GEMM + gates phase (warp-specialized, bf16) ---------
// CTA tile: 128 batch rows x 128 gate cols ({i,f,g,o} x 32 j at j0).
__device__ void phase_layer(char* smem, float* sbias,
                            const __nv_bfloat16* A1, size_t lda1, int KA1,
                            const __nv_bfloat16* A2, int lda2,
                            const __nv_bfloat16* W1, int ldw1, int KW1,
                            const __nv_bfloat16* W2, int ldw2,
                            const float* bih, const float* bhh,
                            float* cbuf, __nv_bfloat16* hdst, float* hfp,
                            int KT)
{
    const int tid  = threadIdx.x;
    const int warp = tid >> 5, lane = tid & 31;
    const int m0 = (blockIdx.x >> 4) * 128;
    const int j0 = (blockIdx.x & 15) * 32;
    const int nch = KT >> 6;             // #k64 chunks (10 or 16)

    if (tid < 128) {
        int n = (tid >> 5) * 512 + j0 + (tid & 31);
        sbias[tid] = bih[n] + bhh[n];
    }

    const uint32_t sA = smem_u32(smem);
    const uint32_t sB = sA + (uint32_t)TILEB;

    if (warp >= 8) {
        // ================= producer path =================
        const int p = tid - 256;                   // 0..127
        const uint32_t dA = sA + (uint32_t)p * ROWB;
        const uint32_t dB = sB + (uint32_t)p * ROWB;
        const int nrow = (p >> 5) * 512 + j0 + (p & 31);
        const __nv_bfloat16* a1r = A1 + (size_t)(m0 + p) * lda1;
        const __nv_bfloat16* a2r = A2 + (size_t)(m0 + p) * lda2 - KA1;
        const __nv_bfloat16* w1r = W1 + (size_t)nrow * ldw1;
        const __nv_bfloat16* w2r = W2 + (size_t)nrow * ldw2 - KW1;

        for (int ch = 0; ch < nch; ch++) {
            int st = ch & (NST - 1);
            int k0 = ch * 64;
            bar_sync(5 + st);                      // stage free?
            const __nv_bfloat16* srcA = (k0 < KA1) ? a1r + k0 : a2r + k0;
            const __nv_bfloat16* srcB = (k0 < KW1) ? w1r + k0 : w2r + k0;
            uint32_t da = dA + (uint32_t)st * STB;
            uint32_t db = dB + (uint32_t)st * STB;
#pragma unroll
            for (int q = 0; q < 8; q++) {          // 8 x 16B = 128B per row
                cp16(da + q * 16u, srcA + q * 8);
                cp16(db + q * 16u, srcB + q * 8);
            }
            asm volatile("cp.async.commit_group;" ::: "memory");
            if (ch > 0) {
                asm volatile("cp.async.wait_group 1;" ::: "memory");
                int pst = (ch - 1) & (NST - 1);
                bar_arrive(1 + pst);               // stage ch-1 full
            }
        }
        asm volatile("cp.async.wait_group 0;" ::: "memory");
        {
            int pst = (nch - 1) & (NST - 1);
            bar_arrive(1 + pst);
        }
    } else {
        // ================= consumer path =================
        const int wm = (warp >> 2) * 64;
        const int wn = (warp & 3) * 32;
        const uint32_t offA = sA + (uint32_t)((lane & 15) * ROWB)
                                 + (uint32_t)((lane >> 4) * 16)
                                 + (uint32_t)wm * ROWB;
        const uint32_t offB = sB + (uint32_t)((lane & 15) * ROWB)
                                 + (uint32_t)((lane >> 4) * 16)
                                 + (uint32_t)wn * ROWB;

        float acc[4][4][4];
#pragma unroll
        for (int mi = 0; mi < 4; mi++)
#pragma unroll
            for (int ni = 0; ni < 4; ni++)
#pragma unroll
                for (int r = 0; r < 4; r++) acc[mi][ni][r] = 0.f;

        for (int ch = 0; ch < nch; ch++) {
            int st = ch & (NST - 1);
            bar_sync(1 + st);                      // wait stage full
            const uint32_t so = (uint32_t)st * STB;
#pragma unroll
            for (int ks = 0; ks < 4; ks++) {       // four k16 steps of k64
                const uint32_t ko = (uint32_t)(ks * 32);   // 16 els * 2B
                // ---- issue ALL fragment loads first (they pipeline) ----
                uint32_t fb0[4], fb1[4], fa0[4], fa1[4], fa2[4], fa3[4];
                LDSM4(fb0, offB + so + ko);                      // n 0-15
                LDSM4(fb1, offB + so + 16u * ROWB + ko);         // n 16-31
                LDSM4(fa0, offA + so + ko);                      // m +0
                LDSM4(fa1, offA + so + 16u * ROWB + ko);         // m +16
                LDSM4(fa2, offA + so + 32u * ROWB + ko);         // m +32
                LDSM4(fa3, offA + so + 48u * ROWB + ko);         // m +48
                // ---- then 16 dependency-free MMAs ----
                mma16(acc[0][0], fa0[0], fa0[1], fa0[2], fa0[3], fb0[0], fb0[2]);
                mma16(acc[0][1], fa0[0], fa0[1], fa0[2], fa0[3], fb0[1], fb0[3]);
                mma16(acc[0][2], fa0[0], fa0[1], fa0[2], fa0[3], fb1[0], fb1[2]);
                mma16(acc[0][3], fa0[0], fa0[1], fa0[2], fa0[3], fb1[1], fb1[3]);
                mma16(acc[1][0], fa1[0], fa1[1], fa1[2], fa1[3], fb0[0], fb0[2]);
                mma16(acc[1][1], fa1[0], fa1[1], fa1[2], fa1[3], fb0[1], fb0[3]);
                mma16(acc[1][2], fa1[0], fa1[1], fa1[2], fa1[3], fb1[0], fb1[2]);
                mma16(acc[1][3], fa1[0], fa1[1], fa1[2], fa1[3], fb1[1], fb1[3]);
                mma16(acc[2][0], fa2[0], fa2[1], fa2[2], fa2[3], fb0[0], fb0[2]);
                mma16(acc[2][1], fa2[0], fa2[1], fa2[2], fa2[3], fb0[1], fb0[3]);
                mma16(acc[2][2], fa2[0], fa2[1], fa2[2], fa2[3], fb1[0], fb1[2]);
                mma16(acc[2][3], fa2[0], fa2[1], fa2[2], fa2[3], fb1[1], fb1[3]);
                mma16(acc[3][0], fa3[0], fa3[1], fa3[2], fa3[3], fb0[0], fb0[2]);
                mma16(acc[3][1], fa3[0], fa3[1], fa3[2], fa3[3], fb0[1], fb0[3]);
                mma16(acc[3][2], fa3[0], fa3[1], fa3[2], fa3[3], fb1[0], fb1[2]);
                mma16(acc[3][3], fa3[0], fa3[1], fa3[2], fa3[3], fb1[1], fb1[3]);
            }
            bar_arrive(5 + st);                    // stage consumed
        }

        __syncthreads();                           // pair with producers below
        {
            const int gid = lane >> 2, t4 = lane & 3;
            float* zb = (float*)smem;
#pragma unroll
            for (int mi = 0; mi < 4; mi++) {
                int r0 = wm + mi * 16 + gid;
#pragma unroll
                for (int ni = 0; ni < 4; ni++) {
                    int c = wn + ni * 8 + t4 * 2;
                    *(float2*)&zb[(size_t)r0 * 132 + c]       = make_float2(acc[mi][ni][0], acc[mi][ni][1]);
                    *(float2*)&zb[(size_t)(r0 + 8) * 132 + c] = make_float2(acc[mi][ni][2], acc[mi][ni][3]);
                }
            }
        }
    }

    if (warp >= 8) __syncthreads();                // producers' pairing sync
    __syncthreads();                               // zb visible to all

    // ---- gate epilogue over ALL 384 threads (warp-per-row, coalesced) ----
    {
        float* zb = (float*)smem;
        for (int idx = tid; idx < 4096; idx += NTHR) {
            const int row = idx >> 5;              // 0..127
            const int j   = idx & 31;
            const int m   = m0 + row;
            const float* zr = zb + (size_t)row * 132;
            float zi = zr[j]      + sbias[j];
            float zf = zr[32 + j] + sbias[32 + j];
            float zg = zr[64 + j] + sbias[64 + j];
            float zo = zr[96 + j] + sbias[96 + j];
            float* cp_ = cbuf + (size_t)m * HD + j0 + j;
            float c = sig_a(zf) * (*cp_) + sig_a(zi) * tanh_a(zg);
            *cp_ = c;
            float h = sig_a(zo) * tanh_a(c);
            hdst[(size_t)m * 1024 + j0 + j] = __float2bfloat16(h);
            if (hfp) hfp[(size_t)m * HD + j0 + j] = h;
        }
    }
    __syncthreads();
}

// ---------------- fc phase: group-local (16 CTAs of one m-group) -------------
__device__ void fc_group(char* smem,
                         const float* __restrict__ fcw,
                         const float* __restrict__ fcb,
                         float* __restrict__ out, int t)
{
    const int gq = blockIdx.x >> 4, jx = blockIdx.x & 15;
    const int r0 = gq * 128 + jx * 8;          // this CTA's 8 batch rows
    const int tid = threadIdx.x;
    float* hs = (float*)smem;                  // 8 x 512 fp32 = 16 KB

    for (int i = tid * 4; i < 8 * HD; i += NTHR * 4) {
        int rr = i >> 9, u = i & 511;
        *(float4*)(hs + rr * HD + u) = ldcg4(g_h1f + (size_t)(r0 + rr) * HD + u);
    }
    __syncthreads();

    if (tid < 256) {
        const int col   = tid & 127;
        const int rbase = tid >> 7;            // 0 or 1; rows rbase+2i
        float a0 = 0.f, a1 = 0.f, a2 = 0.f, a3 = 0.f;
        const float4* w = (const float4*)(fcw + (size_t)col * HD);
        const float* h0p = hs + (rbase + 0) * HD;
        const float* h1p = hs + (rbase + 2) * HD;
        const float* h2p = hs + (rbase + 4) * HD;
        const float* h3p = hs + (rbase + 6) * HD;
#pragma unroll 4
        for (int k4 = 0; k4 < HD / 4; k4++) {
            float4 wv = __ldg(w + k4);
            float4 x0 = *(const float4*)(h0p + k4 * 4);
            float4 x1 = *(const float4*)(h1p + k4 * 4);
            float4 x2 = *(const float4*)(h2p + k4 * 4);
            float4 x3 = *(const float4*)(h3p + k4 * 4);
            a0 += x0.x * wv.x + x0.y * wv.y + x0.z * wv.z + x0.w * wv.w;
            a1 += x1.x * wv.x + x1.y * wv.y + x1.z * wv.z + x1.w * wv.w;
            a2 += x2.x * wv.x + x2.y * wv.y + x2.z * wv.z + x2.w * wv.w;
            a3 += x3.x * wv.x + x3.y * wv.y + x3.z * wv.z + x3.w * wv.w;
        }
        float b = fcb[col];
        float r[4] = {a0 + b, a1 + b, a2 + b, a3 + b};
#pragma unroll
        for (int i = 0; i < 4; i++) {
            int m = r0 + rbase + 2 * i;
            out[(size_t)m * (TDEC * ID) + (size_t)t * ID + col] = r[i];
            g_din[(size_t)m * ID + col] = __float2bfloat16(r[i]);
        }
    }
    __syncthreads();
}

// ---------------- persistent kernel -----------------------------------------
__global__ void __launch_bounds__(NTHR, 1)
lstm_persistent(const float* __restrict__ x,
                const float* __restrict__ Wih0, const float* __restrict__ Whh0,
                const float* __restrict__ bih0, const float* __restrict__ bhh0,
                const float* __restrict__ Wih1, const float* __restrict__ Whh1,
                const float* __restrict__ bih1, const float* __restrict__ bhh1,
                const float* __restrict__ fcw,  const float* __restrict__ fcb,
                float* __restrict__ out)
{
    extern __shared__ char dyn[];        // NST * STB = 147456 B
    __shared__ float s_bias[128];

    // prime EMPTY barriers: one consumer-side arrival round per stage
    if (threadIdx.x < 256) {
        bar_arrive(5); bar_arrive(6); bar_arrive(7); bar_arrive(8);
    }

    init_phase(x, Wih0, Whh0, Wih1, Whh1);
    gridbar();                           // ONLY global barrier

    // ======== encoder: wavefront {layer0[p], layer1[p-1]} per phase ========
    for (int p = 0; p <= TENC; p++) {
        if (p < TENC) {
            int t = p;
            __nv_bfloat16* cur  = (t & 1) ? g_hB : g_hA;
            __nv_bfloat16* prev = (t & 1) ? g_hA : g_hB;
            phase_layer(dyn, s_bias,
                        g_xb + (size_t)t * ID, (size_t)TENC * ID, 128, prev, 1024,
                        g_rWih0, 128, 128, g_rWhh0, 512,
                        bih0, bhh0, g_c0, cur, nullptr, 640);
        }
        if (p >= 1) {
            int t1 = p - 1;
            __nv_bfloat16* cur  = (t1 & 1) ? g_hB : g_hA;
            __nv_bfloat16* prev = (t1 & 1) ? g_hA : g_hB;
            phase_layer(dyn, s_bias,
                        cur, 1024, 512, prev + 512, 1024,
                        g_rWih1, 512, 512, g_rWhh1, 512,
                        bih1, bhh1, g_c1, cur + 512, nullptr, 1024);
        }
        groupbar();
    }

    // ======== decoder: serial per step, group-local barriers ========
    for (int t = 0; t < TDEC; t++) {
        __nv_bfloat16* cur  = (t & 1) ? g_hB : g_hA;   // TENC even: parity ok
        __nv_bfloat16* prev = (t & 1) ? g_hA : g_hB;
        phase_layer(dyn, s_bias,
                    g_din, ID, 128, prev, 1024,
                    g_rWih0, 128, 128, g_rWhh0, 512,
                    bih0, bhh0, g_c0, cur, nullptr, 640);
        groupbar();
        phase_layer(dyn, s_bias,
                    cur, 1024, 512, prev + 512, 1024,
                    g_rWih1, 512, 512, g_rWhh1, 512,
                    bih1, bhh1, g_c1, cur + 512, g_h1f, 1024);
        groupbar();
        fc_group(dyn, fcw, fcb, out, t);
        groupbar();
    }
}

// ---------------- entry ------------------------------------------------------
extern "C" void kernel_launch(void* const* d_in, const int* in_sizes, int n_in,
                              void* d_out, int out_size)
{
    const int smem = NST * STB;          // 147456
    cudaFuncSetAttribute(lstm_persistent,
                         cudaFuncAttributeMaxDynamicSharedMemorySize, smem);
    lstm_persistent<<<NBLK, NTHR, smem>>>(
        (const float*)d_in[0],
        (const float*)d_in[1], (const float*)d_in[2],
        (const float*)d_in[3], (const float*)d_in[4],
        (const float*)d_in[5], (const float*)d_in[6],
        (const float*)d_in[7], (const float*)d_in[8],
        (const float*)d_in[9], (const float*)d_in[10],
        (float*)d_out);
}